// round 3
// baseline (speedup 1.0000x reference)
#include <cuda_runtime.h>
#include <math.h>

#define N_USERS   100000
#define N_ITEMS   50000
#define N_NODES   150000
#define DIM       128
#define KINT      8
#define E_G       1500000
#define NL        65536
#define EL        262144
#define BATCH     1024

#define OUT_PRED  0
#define OUT_GU    1024
#define OUT_HSUB  (1024 + 131072)
#define OUT_PU    (1024 + 2*131072)
#define OUT_PV    (1024 + 2*131072 + 8192)
#define OUT_TOTAL (1024 + 2*131072 + 2*8192)

// ---------------- scratch (device globals; no allocation allowed) -------------
__device__ float g_Y[N_NODES * DIM];      // all_emb @ gnn_W + b
__device__ float g_aggr[N_NODES * DIM];   // scatter accumulator
__device__ float g_xw[NL * DIM];          // local node features @ combined matrix
__device__ float g_lout[NL * DIM];        // gcn scatter accumulator
__device__ float g_PG[257 * DIM];         // local_proj_w @ gcn_w; row 256 = local_proj_b @ gcn_w
__device__ float g_D4[4 * DIM];           // dist_emb @ PG[128:256] + PG[256]
__device__ float g_dinv[NL];
__device__ int   g_deg[NL];
__device__ float g_gu[BATCH * DIM];
__device__ float g_gi[BATCH * DIM];
__device__ float g_ru[BATCH * DIM];
__device__ float g_rv[BATCH * DIM];
__device__ float g_hsub[BATCH * DIM];

__device__ __forceinline__ void red_add_v4(float* p, float4 v) {
    asm volatile("red.global.add.v4.f32 [%0], {%1,%2,%3,%4};"
                 :: "l"(p), "f"(v.x), "f"(v.y), "f"(v.z), "f"(v.w) : "memory");
}

// ---------------- init: zero accumulators, deg=1 ------------------------------
__global__ void init_kernel() {
    int i = blockIdx.x * blockDim.x + threadIdx.x;
    int stride = gridDim.x * blockDim.x;
    float4 z = make_float4(0.f, 0.f, 0.f, 0.f);
    float4* a4 = (float4*)g_aggr;
    for (int k = i; k < N_NODES * DIM / 4; k += stride) a4[k] = z;
    float4* l4 = (float4*)g_lout;
    for (int k = i; k < NL * DIM / 4; k += stride) l4[k] = z;
    for (int k = i; k < NL; k += stride) g_deg[k] = 1;
}

// ---------------- Y = all_emb @ W + b  (fp32 register-tiled SGEMM) -----------
// block: 256 threads, 64 rows. smem: W (64KB) + X tile (32KB) = 96KB dynamic.
__global__ void __launch_bounds__(256) y_gemm(const float* __restrict__ ue,
                                              const float* __restrict__ ie,
                                              const float* __restrict__ W,
                                              const float* __restrict__ bias) {
    extern __shared__ float sm[];
    float4* Wsm = (float4*)sm;               // [128][32]
    float4* Xsm = (float4*)(sm + DIM * DIM); // [64][32]
    int tid = threadIdx.x;
    int r0 = blockIdx.x * 64;

#pragma unroll
    for (int t = 0; t < 16; t++) {
        int idx = tid + t * 256;
        Wsm[idx] = ((const float4*)W)[idx];
    }
#pragma unroll
    for (int t = 0; t < 8; t++) {
        int idx = tid + t * 256;          // 0..2047
        int row = idx >> 5, kq = idx & 31;
        int r = r0 + row;
        float4 v = make_float4(0.f, 0.f, 0.f, 0.f);
        if (r < N_NODES) {
            const float* p = (r < N_USERS) ? (ue + (size_t)r * DIM)
                                           : (ie + (size_t)(r - N_USERS) * DIM);
            v = ((const float4*)p)[kq];
        }
        Xsm[idx] = v;
    }
    __syncthreads();

    int c = tid & 31;    // cols 4c..4c+3
    int rg = tid >> 5;   // rows rg*8..rg*8+7
    float acc[8][4];
#pragma unroll
    for (int r = 0; r < 8; r++)
#pragma unroll
        for (int m = 0; m < 4; m++) acc[r][m] = 0.f;

    for (int k4 = 0; k4 < 32; k4++) {
        float4 w0 = Wsm[(k4 * 4 + 0) * 32 + c];
        float4 w1 = Wsm[(k4 * 4 + 1) * 32 + c];
        float4 w2 = Wsm[(k4 * 4 + 2) * 32 + c];
        float4 w3 = Wsm[(k4 * 4 + 3) * 32 + c];
#pragma unroll
        for (int r = 0; r < 8; r++) {
            float4 xv = Xsm[(rg * 8 + r) * 32 + k4];
            acc[r][0] += xv.x * w0.x + xv.y * w1.x + xv.z * w2.x + xv.w * w3.x;
            acc[r][1] += xv.x * w0.y + xv.y * w1.y + xv.z * w2.y + xv.w * w3.y;
            acc[r][2] += xv.x * w0.z + xv.y * w1.z + xv.z * w2.z + xv.w * w3.z;
            acc[r][3] += xv.x * w0.w + xv.y * w1.w + xv.z * w2.w + xv.w * w3.w;
        }
    }
    float4 bv = ((const float4*)bias)[c];
#pragma unroll
    for (int r = 0; r < 8; r++) {
        int row = r0 + rg * 8 + r;
        if (row < N_NODES) {
            float4 o = make_float4(acc[r][0] + bv.x, acc[r][1] + bv.y,
                                   acc[r][2] + bv.z, acc[r][3] + bv.w);
            ((float4*)g_Y)[(size_t)row * 32 + c] = o;
        }
    }
}

// ---------------- global edge scatter: aggr[dst] += sign * Y[src] ------------
// 2 edges per warp; indices hoisted, sign selected from 2 preloaded scalars.
__global__ void __launch_bounds__(256) edge_scatter(const int* __restrict__ src,
                                                    const int* __restrict__ dst,
                                                    const int* __restrict__ attr,
                                                    const float* __restrict__ sign_emb) {
    int warp = (blockIdx.x * blockDim.x + threadIdx.x) >> 5;
    int lane = threadIdx.x & 31;
    int e0 = warp * 2;
    if (e0 >= E_G) return;
    float sA = __ldg(sign_emb);         // sign_emb[0]
    float sB = __ldg(sign_emb + 1);     // sign_emb[1]
    int e1 = e0 + 1;
    bool has1 = (e1 < E_G);

    int s0 = src[e0];
    int s1 = src[has1 ? e1 : e0];
    int d0 = dst[e0];
    int d1 = dst[has1 ? e1 : e0];
    int a0 = attr[e0];
    int a1 = attr[has1 ? e1 : e0];

    float4 v0 = ((const float4*)g_Y)[(size_t)s0 * 32 + lane];
    float4 v1 = ((const float4*)g_Y)[(size_t)s1 * 32 + lane];

    float sg0 = a0 ? sB : sA;
    float sg1 = a1 ? sB : sA;

    v0.x *= sg0; v0.y *= sg0; v0.z *= sg0; v0.w *= sg0;
    red_add_v4(&g_aggr[(size_t)d0 * DIM + lane * 4], v0);
    if (has1) {
        v1.x *= sg1; v1.y *= sg1; v1.z *= sg1; v1.w *= sg1;
        red_add_v4(&g_aggr[(size_t)d1 * DIM + lane * 4], v1);
    }
}

// ---------------- gather gu/gi: repr = emb + relu(aggr) ----------------------
__global__ void gugi_kernel(const int* __restrict__ root_u, const int* __restrict__ root_i,
                            const float* __restrict__ ue, const float* __restrict__ ie,
                            float* __restrict__ out, int out_size) {
    int g = blockIdx.x * blockDim.x + threadIdx.x; // 2048*32
    int row = g >> 5, lane = g & 31;
    if (row >= 2 * BATCH) return;
    int node; float* dstA;
    int b;
    if (row < BATCH) { b = row; node = root_u[b]; dstA = g_gu; }
    else { b = row - BATCH; node = root_i[b] + N_USERS; dstA = g_gi; }
    const float* emb = (node < N_USERS) ? (ue + (size_t)node * DIM)
                                        : (ie + (size_t)(node - N_USERS) * DIM);
    float4 e4 = ((const float4*)emb)[lane];
    float4 a4 = ((const float4*)g_aggr)[(size_t)node * 32 + lane];
    float4 r = make_float4(e4.x + fmaxf(a4.x, 0.f), e4.y + fmaxf(a4.y, 0.f),
                           e4.z + fmaxf(a4.z, 0.f), e4.w + fmaxf(a4.w, 0.f));
    ((float4*)dstA)[b * 32 + lane] = r;
    if (row < BATCH && out_size >= OUT_TOTAL)
        ((float4*)(out + OUT_GU))[b * 32 + lane] = r;
}

// ---------------- intent heads (both sides) ----------------------------------
__global__ void __launch_bounds__(128) intent_kernel(const float* __restrict__ w1,
                                                     const float* __restrict__ b1,
                                                     const float* __restrict__ w2,
                                                     const float* __restrict__ b2,
                                                     const float* __restrict__ c_u,
                                                     const float* __restrict__ c_v,
                                                     float* __restrict__ out, int out_size) {
    __shared__ float xs[DIM];
    __shared__ float h1[DIM];
    __shared__ float lg[KINT];
    __shared__ float ps[KINT];
    int side = blockIdx.x >> 10;          // 0: user, 1: item
    int b = blockIdx.x & 1023;
    int j = threadIdx.x;
    const float* x = side ? (g_gi + b * DIM) : (g_gu + b * DIM);
    xs[j] = x[j];
    __syncthreads();
    float a = b1[j];
#pragma unroll 8
    for (int k = 0; k < DIM; k++) a += xs[k] * w1[k * DIM + j];
    h1[j] = tanhf(a);
    __syncthreads();
    if (j < KINT) {
        float l = b2[j];
        for (int k = 0; k < DIM; k++) l += h1[k] * w2[k * KINT + j];
        lg[j] = l;
    }
    __syncthreads();
    if (j == 0) {
        float m = lg[0];
        for (int t = 1; t < KINT; t++) m = fmaxf(m, lg[t]);
        float s = 0.f;
        for (int t = 0; t < KINT; t++) { ps[t] = expf(lg[t] - m); s += ps[t]; }
        float inv = 1.f / s;
        for (int t = 0; t < KINT; t++) ps[t] *= inv;
    }
    __syncthreads();
    const float* proto = side ? c_v : c_u;
    float r = 0.f;
#pragma unroll
    for (int t = 0; t < KINT; t++) r += ps[t] * proto[t * DIM + j];
    (side ? g_rv : g_ru)[b * DIM + j] = r;
    if (j < KINT && out_size >= OUT_TOTAL)
        out[(side ? OUT_PV : OUT_PU) + b * KINT + j] = ps[j];
}

// ---------------- PG = local_proj_w @ gcn_w  (row 256 = local_proj_b @ gcn_w) -
__global__ void __launch_bounds__(128) pg_kernel(const float* __restrict__ P,
                                                 const float* __restrict__ Pb,
                                                 const float* __restrict__ G) {
    __shared__ float prow[DIM];
    int m = blockIdx.x;      // 0..256
    int j = threadIdx.x;
    prow[j] = (m < 256) ? P[m * DIM + j] : Pb[j];
    __syncthreads();
    float a = 0.f;
#pragma unroll 8
    for (int k = 0; k < DIM; k++) a += prow[k] * G[k * DIM + j];
    g_PG[m * DIM + j] = a;
}

__global__ void __launch_bounds__(128) d4_kernel(const float* __restrict__ dist_emb) {
    __shared__ float de[DIM];
    int d = blockIdx.x;      // 0..3
    int j = threadIdx.x;
    de[j] = dist_emb[d * DIM + j];
    __syncthreads();
    float a = g_PG[256 * DIM + j];
#pragma unroll 8
    for (int k = 0; k < DIM; k++) a += de[k] * g_PG[(128 + k) * DIM + j];
    g_D4[d * DIM + j] = a;
}

// ---------------- degree / dinv ----------------------------------------------
__global__ void deg_kernel(const int* __restrict__ ldst) {
    int e = blockIdx.x * blockDim.x + threadIdx.x;
    if (e < EL) atomicAdd(&g_deg[ldst[e]], 1);
}
__global__ void dinv_kernel() {
    int i = blockIdx.x * blockDim.x + threadIdx.x;
    if (i < NL) g_dinv[i] = rsqrtf((float)g_deg[i]);
}

// ---------------- xw = repr(x_idx) @ PG_top + D4[dist_label] -----------------
__global__ void __launch_bounds__(256) xw_gemm(const int* __restrict__ x_idx,
                                               const int* __restrict__ dist_label,
                                               const float* __restrict__ ue,
                                               const float* __restrict__ ie) {
    extern __shared__ float sm[];
    float4* Wsm = (float4*)sm;               // PG rows 0..127
    float4* Xsm = (float4*)(sm + DIM * DIM);
    int tid = threadIdx.x;
    int r0 = blockIdx.x * 64;

#pragma unroll
    for (int t = 0; t < 16; t++) {
        int idx = tid + t * 256;
        Wsm[idx] = ((const float4*)g_PG)[idx];
    }
#pragma unroll
    for (int t = 0; t < 8; t++) {
        int idx = tid + t * 256;
        int row = idx >> 5, kq = idx & 31;
        int r = r0 + row;                 // always < NL (65536 = 1024*64)
        int node = x_idx[r];
        const float* p = (node < N_USERS) ? (ue + (size_t)node * DIM)
                                          : (ie + (size_t)(node - N_USERS) * DIM);
        float4 e4 = ((const float4*)p)[kq];
        float4 a4 = ((const float4*)g_aggr)[(size_t)node * 32 + kq];
        Xsm[idx] = make_float4(e4.x + fmaxf(a4.x, 0.f), e4.y + fmaxf(a4.y, 0.f),
                               e4.z + fmaxf(a4.z, 0.f), e4.w + fmaxf(a4.w, 0.f));
    }
    __syncthreads();

    int c = tid & 31;
    int rg = tid >> 5;
    float acc[8][4];
#pragma unroll
    for (int r = 0; r < 8; r++)
#pragma unroll
        for (int m = 0; m < 4; m++) acc[r][m] = 0.f;

    for (int k4 = 0; k4 < 32; k4++) {
        float4 w0 = Wsm[(k4 * 4 + 0) * 32 + c];
        float4 w1 = Wsm[(k4 * 4 + 1) * 32 + c];
        float4 w2 = Wsm[(k4 * 4 + 2) * 32 + c];
        float4 w3 = Wsm[(k4 * 4 + 3) * 32 + c];
#pragma unroll
        for (int r = 0; r < 8; r++) {
            float4 xv = Xsm[(rg * 8 + r) * 32 + k4];
            acc[r][0] += xv.x * w0.x + xv.y * w1.x + xv.z * w2.x + xv.w * w3.x;
            acc[r][1] += xv.x * w0.y + xv.y * w1.y + xv.z * w2.y + xv.w * w3.y;
            acc[r][2] += xv.x * w0.z + xv.y * w1.z + xv.z * w2.z + xv.w * w3.z;
            acc[r][3] += xv.x * w0.w + xv.y * w1.w + xv.z * w2.w + xv.w * w3.w;
        }
    }
#pragma unroll
    for (int r = 0; r < 8; r++) {
        int row = r0 + rg * 8 + r;
        int dl = dist_label[row];
        float4 dv = ((const float4*)g_D4)[dl * 32 + c];
        float4 o = make_float4(acc[r][0] + dv.x, acc[r][1] + dv.y,
                               acc[r][2] + dv.z, acc[r][3] + dv.w);
        ((float4*)g_xw)[(size_t)row * 32 + c] = o;
    }
}

// ---------------- local GCN edge scatter (2 edges/warp) -----------------------
__global__ void __launch_bounds__(256) local_scatter(const int* __restrict__ lsrc,
                                                     const int* __restrict__ ldst) {
    int warp = (blockIdx.x * blockDim.x + threadIdx.x) >> 5;
    int lane = threadIdx.x & 31;
    int e0 = warp * 2;
    if (e0 >= EL) return;
    int e1 = e0 + 1;
    bool has1 = (e1 < EL);

    int s0 = lsrc[e0];
    int s1 = lsrc[has1 ? e1 : e0];
    int d0 = ldst[e0];
    int d1 = ldst[has1 ? e1 : e0];

    float4 v0 = ((const float4*)g_xw)[(size_t)s0 * 32 + lane];
    float4 v1 = ((const float4*)g_xw)[(size_t)s1 * 32 + lane];
    float n0 = g_dinv[s0] * g_dinv[d0];
    float n1 = g_dinv[s1] * g_dinv[d1];

    v0.x *= n0; v0.y *= n0; v0.z *= n0; v0.w *= n0;
    red_add_v4(&g_lout[(size_t)d0 * DIM + lane * 4], v0);
    if (has1) {
        v1.x *= n1; v1.y *= n1; v1.z *= n1; v1.w *= n1;
        red_add_v4(&g_lout[(size_t)d1 * DIM + lane * 4], v1);
    }
}

// ---------------- pool per batch segment + tanh(@pool_w + b) -----------------
__device__ int lower_bound_i(const int* a, int n, int v) {
    int lo = 0, hi = n;
    while (lo < hi) { int m = (lo + hi) >> 1; if (a[m] < v) lo = m + 1; else hi = m; }
    return lo;
}
__global__ void __launch_bounds__(128) pool_kernel(const int* __restrict__ batch,
                                                   const float* __restrict__ gcn_b,
                                                   const float* __restrict__ pool_w,
                                                   const float* __restrict__ pool_b,
                                                   float* __restrict__ out, int out_size) {
    __shared__ int seg[2];
    __shared__ float mean[DIM];
    int b = blockIdx.x;
    int j = threadIdx.x;
    if (j == 0) seg[0] = lower_bound_i(batch, NL, b);
    if (j == 1) seg[1] = lower_bound_i(batch, NL, b + 1);
    __syncthreads();
    int lo = seg[0], hi = seg[1];
    float acc = 0.f;
    for (int i = lo; i < hi; i++) {
        float di = g_dinv[i];
        acc += g_lout[(size_t)i * DIM + j] + di * di * g_xw[(size_t)i * DIM + j];
    }
    int cnt = hi - lo;
    acc += (float)cnt * gcn_b[j];
    mean[j] = (cnt > 0) ? acc / (float)cnt : 0.f;
    __syncthreads();
    float t = pool_b[j];
#pragma unroll 8
    for (int k = 0; k < DIM; k++) t += mean[k] * pool_w[k * DIM + j];
    float h = tanhf(t);
    g_hsub[b * DIM + j] = h;
    if (out_size >= OUT_TOTAL) out[OUT_HSUB + b * DIM + j] = h;
}

// ---------------- final MLP ---------------------------------------------------
__global__ void __launch_bounds__(128) final_kernel(const float* __restrict__ w1,
                                                    const float* __restrict__ b1,
                                                    const float* __restrict__ w2,
                                                    const float* __restrict__ b2,
                                                    float* __restrict__ out) {
    __shared__ float v[4 * DIM];
    __shared__ float hid[64];
    int b = blockIdx.x;
    int j = threadIdx.x;
    v[j]           = g_hsub[b * DIM + j];
    v[DIM + j]     = g_gu[b * DIM + j];
    v[2 * DIM + j] = g_gi[b * DIM + j];
    v[3 * DIM + j] = g_ru[b * DIM + j] * g_rv[b * DIM + j];
    __syncthreads();
    if (j < 64) {
        float a = b1[j];
#pragma unroll 8
        for (int k = 0; k < 4 * DIM; k++) a += v[k] * w1[k * 64 + j];
        hid[j] = fmaxf(a, 0.f) * w2[j];
    }
    __syncthreads();
    if (j == 0) {
        float s = b2[0];
        for (int t = 0; t < 64; t++) s += hid[t];
        out[OUT_PRED + b] = 1.f / (1.f + expf(-s));
    }
}

// ---------------- launch ------------------------------------------------------
extern "C" void kernel_launch(void* const* d_in, const int* in_sizes, int n_in,
                              void* d_out, int out_size) {
    const int*   gei    = (const int*)d_in[0];          // [2, E_G]
    const int*   gea    = (const int*)d_in[1];
    const int*   root_u = (const int*)d_in[2];
    const int*   root_i = (const int*)d_in[3];
    const int*   x_idx  = (const int*)d_in[4];
    const int*   dist_l = (const int*)d_in[5];
    const int*   lei    = (const int*)d_in[6];          // [2, EL]
    const int*   batch  = (const int*)d_in[7];
    const float* ue     = (const float*)d_in[8];
    const float* ie     = (const float*)d_in[9];
    const float* dist_e = (const float*)d_in[10];
    const float* c_u    = (const float*)d_in[11];
    const float* c_v    = (const float*)d_in[12];
    const float* gnn_W  = (const float*)d_in[13];
    const float* gnn_b  = (const float*)d_in[14];
    const float* sign_e = (const float*)d_in[15];
    const float* iw1    = (const float*)d_in[16];
    const float* ib1    = (const float*)d_in[17];
    const float* iw2    = (const float*)d_in[18];
    const float* ib2    = (const float*)d_in[19];
    const float* lpw    = (const float*)d_in[20];
    const float* lpb    = (const float*)d_in[21];
    const float* gcw    = (const float*)d_in[22];
    const float* gcb    = (const float*)d_in[23];
    const float* pow_   = (const float*)d_in[24];
    const float* pob    = (const float*)d_in[25];
    const float* fw1    = (const float*)d_in[26];
    const float* fb1    = (const float*)d_in[27];
    const float* fw2    = (const float*)d_in[28];
    const float* fb2    = (const float*)d_in[29];
    float* out = (float*)d_out;

    cudaFuncSetAttribute(y_gemm,  cudaFuncAttributeMaxDynamicSharedMemorySize, 98304);
    cudaFuncSetAttribute(xw_gemm, cudaFuncAttributeMaxDynamicSharedMemorySize, 98304);

    init_kernel<<<1184, 256>>>();                       // 148 SMs * 2048 threads, ~1 wave
    pg_kernel<<<257, 128>>>(lpw, lpb, gcw);
    d4_kernel<<<4, 128>>>(dist_e);
    deg_kernel<<<EL / 256, 256>>>(lei + EL);
    dinv_kernel<<<NL / 256, 256>>>();

    y_gemm<<<(N_NODES + 63) / 64, 256, 98304>>>(ue, ie, gnn_W, gnn_b);
    edge_scatter<<<(E_G / 2 + 7) / 8, 256>>>(gei, gei + E_G, gea, sign_e);

    gugi_kernel<<<(2 * BATCH * 32) / 256, 256>>>(root_u, root_i, ue, ie, out, out_size);
    intent_kernel<<<2 * BATCH, 128>>>(iw1, ib1, iw2, ib2, c_u, c_v, out, out_size);

    xw_gemm<<<NL / 64, 256, 98304>>>(x_idx, dist_l, ue, ie);
    local_scatter<<<(EL / 2) / 8, 256>>>(lei, lei + EL);
    pool_kernel<<<BATCH, 128>>>(batch, gcb, pow_, pob, out, out_size);
    final_kernel<<<BATCH, 128>>>(fw1, fb1, fw2, fb2, out);
}

// round 4
// speedup vs baseline: 1.5699x; 1.5699x over previous
#include <cuda_runtime.h>
#include <math.h>

#define N_USERS   100000
#define N_ITEMS   50000
#define N_NODES   150000
#define DIM       128
#define KINT      8
#define E_G       1500000
#define NL        65536
#define EL        262144
#define BATCH     1024

#define OUT_PRED  0
#define OUT_GU    1024
#define OUT_HSUB  (1024 + 131072)
#define OUT_PU    (1024 + 2*131072)
#define OUT_PV    (1024 + 2*131072 + 8192)
#define OUT_TOTAL (1024 + 2*131072 + 2*8192)

#define XS 132            // padded smem row stride (floats): conflict-free frag reads
#define GEMM_SMEM (2 * 128 * XS * 4)

// ---------------- scratch (device globals; no allocation allowed) -------------
__device__ float g_Y[N_NODES * DIM];
__device__ float g_aggr[N_NODES * DIM];
__device__ float g_xw[NL * DIM];
__device__ float g_lout[NL * DIM];
__device__ float g_PG[257 * DIM];         // local_proj_w @ gcn_w; row 256 = local_proj_b @ gcn_w
__device__ float g_D4[4 * DIM];           // dist_emb @ PG[128:256] + PG[256]
__device__ float g_dinv[NL];
__device__ int   g_deg[NL];
__device__ float g_gu[BATCH * DIM];
__device__ float g_gi[BATCH * DIM];
__device__ float g_ru[BATCH * DIM];
__device__ float g_rv[BATCH * DIM];
__device__ float g_hsub[BATCH * DIM];

__device__ __forceinline__ void red_add_v4(float* p, float4 v) {
    asm volatile("red.global.add.v4.f32 [%0], {%1,%2,%3,%4};"
                 :: "l"(p), "f"(v.x), "f"(v.y), "f"(v.z), "f"(v.w) : "memory");
}
__device__ __forceinline__ unsigned f2tf32(float f) {
    unsigned r;
    asm("cvt.rna.tf32.f32 %0, %1;" : "=r"(r) : "f"(f));
    return r;
}
__device__ __forceinline__ void mma_tf32(float c[4], unsigned a0, unsigned a1,
                                         unsigned a2, unsigned a3,
                                         unsigned b0, unsigned b1) {
    asm volatile("mma.sync.aligned.m16n8k8.row.col.f32.tf32.tf32.f32 "
                 "{%0,%1,%2,%3}, {%4,%5,%6,%7}, {%8,%9}, {%0,%1,%2,%3};"
                 : "+f"(c[0]), "+f"(c[1]), "+f"(c[2]), "+f"(c[3])
                 : "r"(a0), "r"(a1), "r"(a2), "r"(a3), "r"(b0), "r"(b1));
}

// ---------------- init: zero accumulators, deg=1 ------------------------------
__global__ void init_kernel() {
    int i = blockIdx.x * blockDim.x + threadIdx.x;
    int stride = gridDim.x * blockDim.x;
    float4 z = make_float4(0.f, 0.f, 0.f, 0.f);
    float4* a4 = (float4*)g_aggr;
    for (int k = i; k < N_NODES * DIM / 4; k += stride) a4[k] = z;
    float4* l4 = (float4*)g_lout;
    for (int k = i; k < NL * DIM / 4; k += stride) l4[k] = z;
    for (int k = i; k < NL; k += stride) g_deg[k] = 1;
}

// ---------------- Y = all_emb @ W + b  (tf32 tensor-core GEMM) ---------------
// 256 threads = 8 warps, 128-row tile. Each warp owns 16 rows x 128 cols.
__global__ void __launch_bounds__(256) y_gemm_tc(const float* __restrict__ ue,
                                                 const float* __restrict__ ie,
                                                 const float* __restrict__ W,
                                                 const float* __restrict__ bias) {
    extern __shared__ float sm[];
    float* Wsm = sm;              // [128][XS]
    float* Xsm = sm + 128 * XS;   // [128][XS]
    int tid = threadIdx.x;
    int r0 = blockIdx.x * 128;

#pragma unroll
    for (int t = 0; t < 16; t++) {
        int i = tid + t * 256;
        int row = i >> 5, q = i & 31;
        float4 v = ((const float4*)W)[row * 32 + q];
        *(float4*)&Wsm[row * XS + q * 4] = v;
    }
#pragma unroll
    for (int t = 0; t < 16; t++) {
        int i = tid + t * 256;
        int row = i >> 5, q = i & 31;
        int r = r0 + row;
        float4 v = make_float4(0.f, 0.f, 0.f, 0.f);
        if (r < N_NODES) {
            const float* p = (r < N_USERS) ? (ue + (size_t)r * DIM)
                                           : (ie + (size_t)(r - N_USERS) * DIM);
            v = ((const float4*)p)[q];
        }
        *(float4*)&Xsm[row * XS + q * 4] = v;
    }
    __syncthreads();

    int warp = tid >> 5, lane = tid & 31;
    int gid = lane >> 2, tig = lane & 3;
    int wr = warp * 16;

    float acc[16][4];
#pragma unroll
    for (int n = 0; n < 16; n++)
#pragma unroll
        for (int m = 0; m < 4; m++) acc[n][m] = 0.f;

#pragma unroll
    for (int k = 0; k < 128; k += 8) {
        unsigned a0 = f2tf32(Xsm[(wr + gid) * XS + k + tig]);
        unsigned a1 = f2tf32(Xsm[(wr + gid + 8) * XS + k + tig]);
        unsigned a2 = f2tf32(Xsm[(wr + gid) * XS + k + tig + 4]);
        unsigned a3 = f2tf32(Xsm[(wr + gid + 8) * XS + k + tig + 4]);
#pragma unroll
        for (int n = 0; n < 16; n++) {
            unsigned b0 = f2tf32(Wsm[(k + tig) * XS + n * 8 + gid]);
            unsigned b1 = f2tf32(Wsm[(k + tig + 4) * XS + n * 8 + gid]);
            mma_tf32(acc[n], a0, a1, a2, a3, b0, b1);
        }
    }

    int row0 = r0 + wr + gid;
    int row1 = row0 + 8;
#pragma unroll
    for (int n = 0; n < 16; n++) {
        int c0 = n * 8 + tig * 2;
        float bx = bias[c0], by = bias[c0 + 1];
        if (row0 < N_NODES) {
            float2 o = make_float2(acc[n][0] + bx, acc[n][1] + by);
            *(float2*)&g_Y[(size_t)row0 * DIM + c0] = o;
        }
        if (row1 < N_NODES) {
            float2 o = make_float2(acc[n][2] + bx, acc[n][3] + by);
            *(float2*)&g_Y[(size_t)row1 * DIM + c0] = o;
        }
    }
}

// ---------------- global edge scatter: aggr[dst] += sign * Y[src] ------------
__global__ void __launch_bounds__(256) edge_scatter(const int* __restrict__ src,
                                                    const int* __restrict__ dst,
                                                    const int* __restrict__ attr,
                                                    const float* __restrict__ sign_emb) {
    int warp = (blockIdx.x * blockDim.x + threadIdx.x) >> 5;
    int lane = threadIdx.x & 31;
    int e0 = warp * 2;
    if (e0 >= E_G) return;
    float sA = __ldg(sign_emb);
    float sB = __ldg(sign_emb + 1);
    int e1 = e0 + 1;
    bool has1 = (e1 < E_G);

    int s0 = src[e0];
    int s1 = src[has1 ? e1 : e0];
    int d0 = dst[e0];
    int d1 = dst[has1 ? e1 : e0];
    int a0 = attr[e0];
    int a1 = attr[has1 ? e1 : e0];

    float4 v0 = ((const float4*)g_Y)[(size_t)s0 * 32 + lane];
    float4 v1 = ((const float4*)g_Y)[(size_t)s1 * 32 + lane];

    float sg0 = a0 ? sB : sA;
    float sg1 = a1 ? sB : sA;

    v0.x *= sg0; v0.y *= sg0; v0.z *= sg0; v0.w *= sg0;
    red_add_v4(&g_aggr[(size_t)d0 * DIM + lane * 4], v0);
    if (has1) {
        v1.x *= sg1; v1.y *= sg1; v1.z *= sg1; v1.w *= sg1;
        red_add_v4(&g_aggr[(size_t)d1 * DIM + lane * 4], v1);
    }
}

// ---------------- gather gu/gi: repr = emb + relu(aggr) ----------------------
__global__ void gugi_kernel(const int* __restrict__ root_u, const int* __restrict__ root_i,
                            const float* __restrict__ ue, const float* __restrict__ ie,
                            float* __restrict__ out, int out_size) {
    int g = blockIdx.x * blockDim.x + threadIdx.x;
    int row = g >> 5, lane = g & 31;
    if (row >= 2 * BATCH) return;
    int node; float* dstA;
    int b;
    if (row < BATCH) { b = row; node = root_u[b]; dstA = g_gu; }
    else { b = row - BATCH; node = root_i[b] + N_USERS; dstA = g_gi; }
    const float* emb = (node < N_USERS) ? (ue + (size_t)node * DIM)
                                        : (ie + (size_t)(node - N_USERS) * DIM);
    float4 e4 = ((const float4*)emb)[lane];
    float4 a4 = ((const float4*)g_aggr)[(size_t)node * 32 + lane];
    float4 r = make_float4(e4.x + fmaxf(a4.x, 0.f), e4.y + fmaxf(a4.y, 0.f),
                           e4.z + fmaxf(a4.z, 0.f), e4.w + fmaxf(a4.w, 0.f));
    ((float4*)dstA)[b * 32 + lane] = r;
    if (row < BATCH && out_size >= OUT_TOTAL)
        ((float4*)(out + OUT_GU))[b * 32 + lane] = r;
}

// ---------------- intent heads (both sides) ----------------------------------
__global__ void __launch_bounds__(128) intent_kernel(const float* __restrict__ w1,
                                                     const float* __restrict__ b1,
                                                     const float* __restrict__ w2,
                                                     const float* __restrict__ b2,
                                                     const float* __restrict__ c_u,
                                                     const float* __restrict__ c_v,
                                                     float* __restrict__ out, int out_size) {
    __shared__ float xs[DIM];
    __shared__ float h1[DIM];
    __shared__ float lg[KINT];
    __shared__ float ps[KINT];
    int side = blockIdx.x >> 10;
    int b = blockIdx.x & 1023;
    int j = threadIdx.x;
    const float* x = side ? (g_gi + b * DIM) : (g_gu + b * DIM);
    xs[j] = x[j];
    __syncthreads();
    float a = b1[j];
#pragma unroll 8
    for (int k = 0; k < DIM; k++) a += xs[k] * w1[k * DIM + j];
    h1[j] = tanhf(a);
    __syncthreads();
    if (j < KINT) {
        float l = b2[j];
        for (int k = 0; k < DIM; k++) l += h1[k] * w2[k * KINT + j];
        lg[j] = l;
    }
    __syncthreads();
    if (j == 0) {
        float m = lg[0];
        for (int t = 1; t < KINT; t++) m = fmaxf(m, lg[t]);
        float s = 0.f;
        for (int t = 0; t < KINT; t++) { ps[t] = expf(lg[t] - m); s += ps[t]; }
        float inv = 1.f / s;
        for (int t = 0; t < KINT; t++) ps[t] *= inv;
    }
    __syncthreads();
    const float* proto = side ? c_v : c_u;
    float r = 0.f;
#pragma unroll
    for (int t = 0; t < KINT; t++) r += ps[t] * proto[t * DIM + j];
    (side ? g_rv : g_ru)[b * DIM + j] = r;
    if (j < KINT && out_size >= OUT_TOTAL)
        out[(side ? OUT_PV : OUT_PU) + b * KINT + j] = ps[j];
}

// ---------------- PG = local_proj_w @ gcn_w ----------------------------------
__global__ void __launch_bounds__(128) pg_kernel(const float* __restrict__ P,
                                                 const float* __restrict__ Pb,
                                                 const float* __restrict__ G) {
    __shared__ float prow[DIM];
    int m = blockIdx.x;
    int j = threadIdx.x;
    prow[j] = (m < 256) ? P[m * DIM + j] : Pb[j];
    __syncthreads();
    float a = 0.f;
#pragma unroll 8
    for (int k = 0; k < DIM; k++) a += prow[k] * G[k * DIM + j];
    g_PG[m * DIM + j] = a;
}

__global__ void __launch_bounds__(128) d4_kernel(const float* __restrict__ dist_emb) {
    __shared__ float de[DIM];
    int d = blockIdx.x;
    int j = threadIdx.x;
    de[j] = dist_emb[d * DIM + j];
    __syncthreads();
    float a = g_PG[256 * DIM + j];
#pragma unroll 8
    for (int k = 0; k < DIM; k++) a += de[k] * g_PG[(128 + k) * DIM + j];
    g_D4[d * DIM + j] = a;
}

// ---------------- degree / dinv ----------------------------------------------
__global__ void deg_kernel(const int* __restrict__ ldst) {
    int e = blockIdx.x * blockDim.x + threadIdx.x;
    if (e < EL) atomicAdd(&g_deg[ldst[e]], 1);
}
__global__ void dinv_kernel() {
    int i = blockIdx.x * blockDim.x + threadIdx.x;
    if (i < NL) g_dinv[i] = rsqrtf((float)g_deg[i]);
}

// ---------------- xw = repr(x_idx) @ PG_top + D4[dist_label]  (tf32 TC) ------
__global__ void __launch_bounds__(256) xw_gemm_tc(const int* __restrict__ x_idx,
                                                  const int* __restrict__ dist_label,
                                                  const float* __restrict__ ue,
                                                  const float* __restrict__ ie) {
    extern __shared__ float sm[];
    float* Wsm = sm;              // PG rows 0..127
    float* Xsm = sm + 128 * XS;
    int tid = threadIdx.x;
    int r0 = blockIdx.x * 128;    // NL = 512 * 128, no guards

#pragma unroll
    for (int t = 0; t < 16; t++) {
        int i = tid + t * 256;
        int row = i >> 5, q = i & 31;
        float4 v = ((const float4*)g_PG)[row * 32 + q];
        *(float4*)&Wsm[row * XS + q * 4] = v;
    }
#pragma unroll
    for (int t = 0; t < 16; t++) {
        int i = tid + t * 256;
        int row = i >> 5, q = i & 31;
        int r = r0 + row;
        int node = x_idx[r];
        const float* p = (node < N_USERS) ? (ue + (size_t)node * DIM)
                                          : (ie + (size_t)(node - N_USERS) * DIM);
        float4 e4 = ((const float4*)p)[q];
        float4 a4 = ((const float4*)g_aggr)[(size_t)node * 32 + q];
        float4 v = make_float4(e4.x + fmaxf(a4.x, 0.f), e4.y + fmaxf(a4.y, 0.f),
                               e4.z + fmaxf(a4.z, 0.f), e4.w + fmaxf(a4.w, 0.f));
        *(float4*)&Xsm[row * XS + q * 4] = v;
    }
    __syncthreads();

    int warp = tid >> 5, lane = tid & 31;
    int gid = lane >> 2, tig = lane & 3;
    int wr = warp * 16;

    float acc[16][4];
#pragma unroll
    for (int n = 0; n < 16; n++)
#pragma unroll
        for (int m = 0; m < 4; m++) acc[n][m] = 0.f;

#pragma unroll
    for (int k = 0; k < 128; k += 8) {
        unsigned a0 = f2tf32(Xsm[(wr + gid) * XS + k + tig]);
        unsigned a1 = f2tf32(Xsm[(wr + gid + 8) * XS + k + tig]);
        unsigned a2 = f2tf32(Xsm[(wr + gid) * XS + k + tig + 4]);
        unsigned a3 = f2tf32(Xsm[(wr + gid + 8) * XS + k + tig + 4]);
#pragma unroll
        for (int n = 0; n < 16; n++) {
            unsigned b0 = f2tf32(Wsm[(k + tig) * XS + n * 8 + gid]);
            unsigned b1 = f2tf32(Wsm[(k + tig + 4) * XS + n * 8 + gid]);
            mma_tf32(acc[n], a0, a1, a2, a3, b0, b1);
        }
    }

    int row0 = r0 + wr + gid;
    int row1 = row0 + 8;
    int dl0 = dist_label[row0];
    int dl1 = dist_label[row1];
#pragma unroll
    for (int n = 0; n < 16; n++) {
        int c0 = n * 8 + tig * 2;
        float2 dv0 = *(const float2*)&g_D4[dl0 * DIM + c0];
        float2 dv1 = *(const float2*)&g_D4[dl1 * DIM + c0];
        float2 o0 = make_float2(acc[n][0] + dv0.x, acc[n][1] + dv0.y);
        float2 o1 = make_float2(acc[n][2] + dv1.x, acc[n][3] + dv1.y);
        *(float2*)&g_xw[(size_t)row0 * DIM + c0] = o0;
        *(float2*)&g_xw[(size_t)row1 * DIM + c0] = o1;
    }
}

// ---------------- local GCN edge scatter (2 edges/warp) -----------------------
__global__ void __launch_bounds__(256) local_scatter(const int* __restrict__ lsrc,
                                                     const int* __restrict__ ldst) {
    int warp = (blockIdx.x * blockDim.x + threadIdx.x) >> 5;
    int lane = threadIdx.x & 31;
    int e0 = warp * 2;
    if (e0 >= EL) return;
    int e1 = e0 + 1;
    bool has1 = (e1 < EL);

    int s0 = lsrc[e0];
    int s1 = lsrc[has1 ? e1 : e0];
    int d0 = ldst[e0];
    int d1 = ldst[has1 ? e1 : e0];

    float4 v0 = ((const float4*)g_xw)[(size_t)s0 * 32 + lane];
    float4 v1 = ((const float4*)g_xw)[(size_t)s1 * 32 + lane];
    float n0 = g_dinv[s0] * g_dinv[d0];
    float n1 = g_dinv[s1] * g_dinv[d1];

    v0.x *= n0; v0.y *= n0; v0.z *= n0; v0.w *= n0;
    red_add_v4(&g_lout[(size_t)d0 * DIM + lane * 4], v0);
    if (has1) {
        v1.x *= n1; v1.y *= n1; v1.z *= n1; v1.w *= n1;
        red_add_v4(&g_lout[(size_t)d1 * DIM + lane * 4], v1);
    }
}

// ---------------- pool per batch segment + tanh(@pool_w + b) -----------------
__device__ int lower_bound_i(const int* a, int n, int v) {
    int lo = 0, hi = n;
    while (lo < hi) { int m = (lo + hi) >> 1; if (a[m] < v) lo = m + 1; else hi = m; }
    return lo;
}
__global__ void __launch_bounds__(128) pool_kernel(const int* __restrict__ batch,
                                                   const float* __restrict__ gcn_b,
                                                   const float* __restrict__ pool_w,
                                                   const float* __restrict__ pool_b,
                                                   float* __restrict__ out, int out_size) {
    __shared__ int seg[2];
    __shared__ float mean[DIM];
    int b = blockIdx.x;
    int j = threadIdx.x;
    if (j == 0) seg[0] = lower_bound_i(batch, NL, b);
    if (j == 1) seg[1] = lower_bound_i(batch, NL, b + 1);
    __syncthreads();
    int lo = seg[0], hi = seg[1];
    float acc = 0.f;
    for (int i = lo; i < hi; i++) {
        float di = g_dinv[i];
        acc += g_lout[(size_t)i * DIM + j] + di * di * g_xw[(size_t)i * DIM + j];
    }
    int cnt = hi - lo;
    acc += (float)cnt * gcn_b[j];
    mean[j] = (cnt > 0) ? acc / (float)cnt : 0.f;
    __syncthreads();
    float t = pool_b[j];
#pragma unroll 8
    for (int k = 0; k < DIM; k++) t += mean[k] * pool_w[k * DIM + j];
    float h = tanhf(t);
    g_hsub[b * DIM + j] = h;
    if (out_size >= OUT_TOTAL) out[OUT_HSUB + b * DIM + j] = h;
}

// ---------------- final MLP ---------------------------------------------------
__global__ void __launch_bounds__(128) final_kernel(const float* __restrict__ w1,
                                                    const float* __restrict__ b1,
                                                    const float* __restrict__ w2,
                                                    const float* __restrict__ b2,
                                                    float* __restrict__ out) {
    __shared__ float v[4 * DIM];
    __shared__ float hid[64];
    int b = blockIdx.x;
    int j = threadIdx.x;
    v[j]           = g_hsub[b * DIM + j];
    v[DIM + j]     = g_gu[b * DIM + j];
    v[2 * DIM + j] = g_gi[b * DIM + j];
    v[3 * DIM + j] = g_ru[b * DIM + j] * g_rv[b * DIM + j];
    __syncthreads();
    if (j < 64) {
        float a = b1[j];
#pragma unroll 8
        for (int k = 0; k < 4 * DIM; k++) a += v[k] * w1[k * 64 + j];
        hid[j] = fmaxf(a, 0.f) * w2[j];
    }
    __syncthreads();
    if (j == 0) {
        float s = b2[0];
        for (int t = 0; t < 64; t++) s += hid[t];
        out[OUT_PRED + b] = 1.f / (1.f + expf(-s));
    }
}

// ---------------- launch ------------------------------------------------------
extern "C" void kernel_launch(void* const* d_in, const int* in_sizes, int n_in,
                              void* d_out, int out_size) {
    const int*   gei    = (const int*)d_in[0];
    const int*   gea    = (const int*)d_in[1];
    const int*   root_u = (const int*)d_in[2];
    const int*   root_i = (const int*)d_in[3];
    const int*   x_idx  = (const int*)d_in[4];
    const int*   dist_l = (const int*)d_in[5];
    const int*   lei    = (const int*)d_in[6];
    const int*   batch  = (const int*)d_in[7];
    const float* ue     = (const float*)d_in[8];
    const float* ie     = (const float*)d_in[9];
    const float* dist_e = (const float*)d_in[10];
    const float* c_u    = (const float*)d_in[11];
    const float* c_v    = (const float*)d_in[12];
    const float* gnn_W  = (const float*)d_in[13];
    const float* gnn_b  = (const float*)d_in[14];
    const float* sign_e = (const float*)d_in[15];
    const float* iw1    = (const float*)d_in[16];
    const float* ib1    = (const float*)d_in[17];
    const float* iw2    = (const float*)d_in[18];
    const float* ib2    = (const float*)d_in[19];
    const float* lpw    = (const float*)d_in[20];
    const float* lpb    = (const float*)d_in[21];
    const float* gcw    = (const float*)d_in[22];
    const float* gcb    = (const float*)d_in[23];
    const float* pow_   = (const float*)d_in[24];
    const float* pob    = (const float*)d_in[25];
    const float* fw1    = (const float*)d_in[26];
    const float* fb1    = (const float*)d_in[27];
    const float* fw2    = (const float*)d_in[28];
    const float* fb2    = (const float*)d_in[29];
    float* out = (float*)d_out;

    cudaFuncSetAttribute(y_gemm_tc,  cudaFuncAttributeMaxDynamicSharedMemorySize, GEMM_SMEM);
    cudaFuncSetAttribute(xw_gemm_tc, cudaFuncAttributeMaxDynamicSharedMemorySize, GEMM_SMEM);

    init_kernel<<<1184, 256>>>();
    pg_kernel<<<257, 128>>>(lpw, lpb, gcw);
    d4_kernel<<<4, 128>>>(dist_e);
    deg_kernel<<<EL / 256, 256>>>(lei + EL);
    dinv_kernel<<<NL / 256, 256>>>();

    y_gemm_tc<<<(N_NODES + 127) / 128, 256, GEMM_SMEM>>>(ue, ie, gnn_W, gnn_b);
    edge_scatter<<<(E_G / 2 + 7) / 8, 256>>>(gei, gei + E_G, gea, sign_e);

    gugi_kernel<<<(2 * BATCH * 32) / 256, 256>>>(root_u, root_i, ue, ie, out, out_size);
    intent_kernel<<<2 * BATCH, 128>>>(iw1, ib1, iw2, ib2, c_u, c_v, out, out_size);

    xw_gemm_tc<<<NL / 128, 256, GEMM_SMEM>>>(x_idx, dist_l, ue, ie);
    local_scatter<<<(EL / 2) / 8, 256>>>(lei, lei + EL);
    pool_kernel<<<BATCH, 128>>>(batch, gcb, pow_, pob, out, out_size);
    final_kernel<<<BATCH, 128>>>(fw1, fb1, fw2, fb2, out);
}

// round 5
// speedup vs baseline: 1.8622x; 1.1862x over previous
#include <cuda_runtime.h>
#include <math.h>

#define N_USERS   100000
#define N_ITEMS   50000
#define N_NODES   150000
#define DIM       128
#define KINT      8
#define E_G       1500000
#define NL        65536
#define EL        262144
#define BATCH     1024

#define OUT_PRED  0
#define OUT_GU    1024
#define OUT_HSUB  (1024 + 131072)
#define OUT_PU    (1024 + 2*131072)
#define OUT_PV    (1024 + 2*131072 + 8192)
#define OUT_TOTAL (1024 + 2*131072 + 2*8192)

#define XS 132            // padded smem row stride (floats)
#define GEMM_SMEM (2 * 128 * XS * 4)

#define SCAN_B 1024
#define NSEG ((N_NODES + SCAN_B - 1) / SCAN_B)   // 147

// ---------------- scratch (device globals; no allocation allowed) -------------
__device__ float g_Y[N_NODES * DIM];
__device__ float g_aggr[N_NODES * DIM];
__device__ float g_xw[NL * DIM];
__device__ float g_lout[NL * DIM];
__device__ float g_PG[257 * DIM];
__device__ float g_D4[4 * DIM];
__device__ float g_dinv[NL];
__device__ int   g_deg[NL];
__device__ float g_gu[BATCH * DIM];
__device__ float g_gi[BATCH * DIM];
__device__ float g_ru[BATCH * DIM];
__device__ float g_rv[BATCH * DIM];
__device__ float g_hsub[BATCH * DIM];
// CSR sort scratch for global edges
__device__ int   g_cnt[N_NODES];     // counts -> start offsets
__device__ int   g_cur[N_NODES];     // fill cursor -> end offsets
__device__ int   g_bsum[NSEG];
__device__ int   g_epack[E_G];       // src | (attr << 24)

__device__ __forceinline__ void red_add_v4(float* p, float4 v) {
    asm volatile("red.global.add.v4.f32 [%0], {%1,%2,%3,%4};"
                 :: "l"(p), "f"(v.x), "f"(v.y), "f"(v.z), "f"(v.w) : "memory");
}
__device__ __forceinline__ unsigned f2tf32(float f) {
    unsigned r;
    asm("cvt.rna.tf32.f32 %0, %1;" : "=r"(r) : "f"(f));
    return r;
}
__device__ __forceinline__ void mma_tf32(float c[4], unsigned a0, unsigned a1,
                                         unsigned a2, unsigned a3,
                                         unsigned b0, unsigned b1) {
    asm volatile("mma.sync.aligned.m16n8k8.row.col.f32.tf32.tf32.f32 "
                 "{%0,%1,%2,%3}, {%4,%5,%6,%7}, {%8,%9}, {%0,%1,%2,%3};"
                 : "+f"(c[0]), "+f"(c[1]), "+f"(c[2]), "+f"(c[3])
                 : "r"(a0), "r"(a1), "r"(a2), "r"(a3), "r"(b0), "r"(b1));
}

// ---------------- init: zero g_lout + g_cnt, deg=1 ---------------------------
__global__ void init_kernel() {
    int i = blockIdx.x * blockDim.x + threadIdx.x;
    int stride = gridDim.x * blockDim.x;
    float4 z = make_float4(0.f, 0.f, 0.f, 0.f);
    float4* l4 = (float4*)g_lout;
    for (int k = i; k < NL * DIM / 4; k += stride) l4[k] = z;
    for (int k = i; k < NL; k += stride) g_deg[k] = 1;
    for (int k = i; k < N_NODES; k += stride) g_cnt[k] = 0;
}

// ---------------- CSR build: histogram, scan, fill ----------------------------
__global__ void hist_kernel(const int* __restrict__ dst) {
    int e = blockIdx.x * blockDim.x + threadIdx.x;
    if (e < E_G) atomicAdd(&g_cnt[dst[e]], 1);
}

__global__ void __launch_bounds__(SCAN_B) scan_a_kernel() {
    __shared__ int sh[SCAN_B];
    int tid = threadIdx.x;
    int i = blockIdx.x * SCAN_B + tid;
    sh[tid] = (i < N_NODES) ? g_cnt[i] : 0;
    __syncthreads();
    for (int s = SCAN_B / 2; s > 0; s >>= 1) {
        if (tid < s) sh[tid] += sh[tid + s];
        __syncthreads();
    }
    if (tid == 0) g_bsum[blockIdx.x] = sh[0];
}

__global__ void __launch_bounds__(256) scan_b_kernel() {
    __shared__ int sh[256];
    int tid = threadIdx.x;
    sh[tid] = (tid < NSEG) ? g_bsum[tid] : 0;
    __syncthreads();
    // inclusive Hillis-Steele
    for (int ofs = 1; ofs < 256; ofs <<= 1) {
        int t = (tid >= ofs) ? sh[tid - ofs] : 0;
        __syncthreads();
        sh[tid] += t;
        __syncthreads();
    }
    if (tid < NSEG) g_bsum[tid] = sh[tid] - ((tid < NSEG) ? 0 : 0) - ((tid < NSEG) ? g_bsum[tid] : 0) + g_bsum[tid] - g_bsum[tid] + (tid == 0 ? 0 : 0) + (sh[tid] - g_bsum[tid]) - (sh[tid] - g_bsum[tid]) + (sh[tid] - g_bsum[tid]);
}

// NOTE: the expression above is error-prone; replaced by clean version below.
__global__ void __launch_bounds__(256) scan_b2_kernel() {
    __shared__ int sh[256];
    int tid = threadIdx.x;
    int v = (tid < NSEG) ? g_bsum[tid] : 0;
    sh[tid] = v;
    __syncthreads();
    for (int ofs = 1; ofs < 256; ofs <<= 1) {
        int t = (tid >= ofs) ? sh[tid - ofs] : 0;
        __syncthreads();
        sh[tid] += t;
        __syncthreads();
    }
    if (tid < NSEG) g_bsum[tid] = sh[tid] - v;   // exclusive
}

__global__ void __launch_bounds__(SCAN_B) scan_c_kernel() {
    __shared__ int sh[SCAN_B];
    int tid = threadIdx.x;
    int i = blockIdx.x * SCAN_B + tid;
    int v = (i < N_NODES) ? g_cnt[i] : 0;
    sh[tid] = v;
    __syncthreads();
    for (int ofs = 1; ofs < SCAN_B; ofs <<= 1) {
        int t = (tid >= ofs) ? sh[tid - ofs] : 0;
        __syncthreads();
        sh[tid] += t;
        __syncthreads();
    }
    if (i < N_NODES) {
        int excl = sh[tid] - v + g_bsum[blockIdx.x];
        g_cnt[i] = excl;      // start offset
        g_cur[i] = excl;      // fill cursor
    }
}

__global__ void fill_kernel(const int* __restrict__ src,
                            const int* __restrict__ dst,
                            const int* __restrict__ attr) {
    int e = blockIdx.x * blockDim.x + threadIdx.x;
    if (e >= E_G) return;
    int d = dst[e];
    int pos = atomicAdd(&g_cur[d], 1);
    g_epack[pos] = src[e] | (attr[e] << 24);
}

// ---------------- Y = all_emb @ W + b  (tf32 tensor-core GEMM) ---------------
__global__ void __launch_bounds__(256) y_gemm_tc(const float* __restrict__ ue,
                                                 const float* __restrict__ ie,
                                                 const float* __restrict__ W,
                                                 const float* __restrict__ bias) {
    extern __shared__ float sm[];
    float* Wsm = sm;
    float* Xsm = sm + 128 * XS;
    int tid = threadIdx.x;
    int r0 = blockIdx.x * 128;

#pragma unroll
    for (int t = 0; t < 16; t++) {
        int i = tid + t * 256;
        int row = i >> 5, q = i & 31;
        float4 v = ((const float4*)W)[row * 32 + q];
        *(float4*)&Wsm[row * XS + q * 4] = v;
    }
#pragma unroll
    for (int t = 0; t < 16; t++) {
        int i = tid + t * 256;
        int row = i >> 5, q = i & 31;
        int r = r0 + row;
        float4 v = make_float4(0.f, 0.f, 0.f, 0.f);
        if (r < N_NODES) {
            const float* p = (r < N_USERS) ? (ue + (size_t)r * DIM)
                                           : (ie + (size_t)(r - N_USERS) * DIM);
            v = ((const float4*)p)[q];
        }
        *(float4*)&Xsm[row * XS + q * 4] = v;
    }
    __syncthreads();

    int warp = tid >> 5, lane = tid & 31;
    int gid = lane >> 2, tig = lane & 3;
    int wr = warp * 16;

    float acc[16][4];
#pragma unroll
    for (int n = 0; n < 16; n++)
#pragma unroll
        for (int m = 0; m < 4; m++) acc[n][m] = 0.f;

#pragma unroll
    for (int k = 0; k < 128; k += 8) {
        unsigned a0 = f2tf32(Xsm[(wr + gid) * XS + k + tig]);
        unsigned a1 = f2tf32(Xsm[(wr + gid + 8) * XS + k + tig]);
        unsigned a2 = f2tf32(Xsm[(wr + gid) * XS + k + tig + 4]);
        unsigned a3 = f2tf32(Xsm[(wr + gid + 8) * XS + k + tig + 4]);
#pragma unroll
        for (int n = 0; n < 16; n++) {
            unsigned b0 = f2tf32(Wsm[(k + tig) * XS + n * 8 + gid]);
            unsigned b1 = f2tf32(Wsm[(k + tig + 4) * XS + n * 8 + gid]);
            mma_tf32(acc[n], a0, a1, a2, a3, b0, b1);
        }
    }

    int row0 = r0 + wr + gid;
    int row1 = row0 + 8;
#pragma unroll
    for (int n = 0; n < 16; n++) {
        int c0 = n * 8 + tig * 2;
        float bx = bias[c0], by = bias[c0 + 1];
        if (row0 < N_NODES) {
            float2 o = make_float2(acc[n][0] + bx, acc[n][1] + by);
            *(float2*)&g_Y[(size_t)row0 * DIM + c0] = o;
        }
        if (row1 < N_NODES) {
            float2 o = make_float2(acc[n][2] + bx, acc[n][3] + by);
            *(float2*)&g_Y[(size_t)row1 * DIM + c0] = o;
        }
    }
}

// ---------------- aggr[d] = sum over in-edges of sign * Y[src]  (gather) -----
// one warp per dst node; CSR built by sort kernels; plain store, no atomics.
__global__ void __launch_bounds__(256) gather_aggr(const float* __restrict__ sign_emb) {
    int warp = (blockIdx.x * blockDim.x + threadIdx.x) >> 5;
    int lane = threadIdx.x & 31;
    if (warp >= N_NODES) return;
    float sA = __ldg(sign_emb);
    float sB = __ldg(sign_emb + 1);
    int p   = g_cnt[warp];
    int end = g_cur[warp];
    float4 acc = make_float4(0.f, 0.f, 0.f, 0.f);
    for (; p + 1 < end; p += 2) {
        int pk0 = g_epack[p];
        int pk1 = g_epack[p + 1];
        int s0 = pk0 & 0xFFFFFF;
        int s1 = pk1 & 0xFFFFFF;
        float4 v0 = ((const float4*)g_Y)[(size_t)s0 * 32 + lane];
        float4 v1 = ((const float4*)g_Y)[(size_t)s1 * 32 + lane];
        float sg0 = (pk0 >> 24) ? sB : sA;
        float sg1 = (pk1 >> 24) ? sB : sA;
        acc.x += sg0 * v0.x + sg1 * v1.x;
        acc.y += sg0 * v0.y + sg1 * v1.y;
        acc.z += sg0 * v0.z + sg1 * v1.z;
        acc.w += sg0 * v0.w + sg1 * v1.w;
    }
    if (p < end) {
        int pk = g_epack[p];
        int s = pk & 0xFFFFFF;
        float sg = (pk >> 24) ? sB : sA;
        float4 v = ((const float4*)g_Y)[(size_t)s * 32 + lane];
        acc.x += sg * v.x; acc.y += sg * v.y; acc.z += sg * v.z; acc.w += sg * v.w;
    }
    ((float4*)g_aggr)[(size_t)warp * 32 + lane] = acc;
}

// ---------------- gather gu/gi: repr = emb + relu(aggr) ----------------------
__global__ void gugi_kernel(const int* __restrict__ root_u, const int* __restrict__ root_i,
                            const float* __restrict__ ue, const float* __restrict__ ie,
                            float* __restrict__ out, int out_size) {
    int g = blockIdx.x * blockDim.x + threadIdx.x;
    int row = g >> 5, lane = g & 31;
    if (row >= 2 * BATCH) return;
    int node; float* dstA;
    int b;
    if (row < BATCH) { b = row; node = root_u[b]; dstA = g_gu; }
    else { b = row - BATCH; node = root_i[b] + N_USERS; dstA = g_gi; }
    const float* emb = (node < N_USERS) ? (ue + (size_t)node * DIM)
                                        : (ie + (size_t)(node - N_USERS) * DIM);
    float4 e4 = ((const float4*)emb)[lane];
    float4 a4 = ((const float4*)g_aggr)[(size_t)node * 32 + lane];
    float4 r = make_float4(e4.x + fmaxf(a4.x, 0.f), e4.y + fmaxf(a4.y, 0.f),
                           e4.z + fmaxf(a4.z, 0.f), e4.w + fmaxf(a4.w, 0.f));
    ((float4*)dstA)[b * 32 + lane] = r;
    if (row < BATCH && out_size >= OUT_TOTAL)
        ((float4*)(out + OUT_GU))[b * 32 + lane] = r;
}

// ---------------- intent heads (both sides) ----------------------------------
__global__ void __launch_bounds__(128) intent_kernel(const float* __restrict__ w1,
                                                     const float* __restrict__ b1,
                                                     const float* __restrict__ w2,
                                                     const float* __restrict__ b2,
                                                     const float* __restrict__ c_u,
                                                     const float* __restrict__ c_v,
                                                     float* __restrict__ out, int out_size) {
    __shared__ float xs[DIM];
    __shared__ float h1[DIM];
    __shared__ float lg[KINT];
    __shared__ float ps[KINT];
    int side = blockIdx.x >> 10;
    int b = blockIdx.x & 1023;
    int j = threadIdx.x;
    const float* x = side ? (g_gi + b * DIM) : (g_gu + b * DIM);
    xs[j] = x[j];
    __syncthreads();
    float a = b1[j];
#pragma unroll 8
    for (int k = 0; k < DIM; k++) a += xs[k] * w1[k * DIM + j];
    h1[j] = tanhf(a);
    __syncthreads();
    if (j < KINT) {
        float l = b2[j];
        for (int k = 0; k < DIM; k++) l += h1[k] * w2[k * KINT + j];
        lg[j] = l;
    }
    __syncthreads();
    if (j == 0) {
        float m = lg[0];
        for (int t = 1; t < KINT; t++) m = fmaxf(m, lg[t]);
        float s = 0.f;
        for (int t = 0; t < KINT; t++) { ps[t] = expf(lg[t] - m); s += ps[t]; }
        float inv = 1.f / s;
        for (int t = 0; t < KINT; t++) ps[t] *= inv;
    }
    __syncthreads();
    const float* proto = side ? c_v : c_u;
    float r = 0.f;
#pragma unroll
    for (int t = 0; t < KINT; t++) r += ps[t] * proto[t * DIM + j];
    (side ? g_rv : g_ru)[b * DIM + j] = r;
    if (j < KINT && out_size >= OUT_TOTAL)
        out[(side ? OUT_PV : OUT_PU) + b * KINT + j] = ps[j];
}

// ---------------- PG = local_proj_w @ gcn_w ----------------------------------
__global__ void __launch_bounds__(128) pg_kernel(const float* __restrict__ P,
                                                 const float* __restrict__ Pb,
                                                 const float* __restrict__ G) {
    __shared__ float prow[DIM];
    int m = blockIdx.x;
    int j = threadIdx.x;
    prow[j] = (m < 256) ? P[m * DIM + j] : Pb[j];
    __syncthreads();
    float a = 0.f;
#pragma unroll 8
    for (int k = 0; k < DIM; k++) a += prow[k] * G[k * DIM + j];
    g_PG[m * DIM + j] = a;
}

__global__ void __launch_bounds__(128) d4_kernel(const float* __restrict__ dist_emb) {
    __shared__ float de[DIM];
    int d = blockIdx.x;
    int j = threadIdx.x;
    de[j] = dist_emb[d * DIM + j];
    __syncthreads();
    float a = g_PG[256 * DIM + j];
#pragma unroll 8
    for (int k = 0; k < DIM; k++) a += de[k] * g_PG[(128 + k) * DIM + j];
    g_D4[d * DIM + j] = a;
}

// ---------------- degree / dinv ----------------------------------------------
__global__ void deg_kernel(const int* __restrict__ ldst) {
    int e = blockIdx.x * blockDim.x + threadIdx.x;
    if (e < EL) atomicAdd(&g_deg[ldst[e]], 1);
}
__global__ void dinv_kernel() {
    int i = blockIdx.x * blockDim.x + threadIdx.x;
    if (i < NL) g_dinv[i] = rsqrtf((float)g_deg[i]);
}

// ---------------- xw = repr(x_idx) @ PG_top + D4[dist_label]  (tf32 TC) ------
__global__ void __launch_bounds__(256) xw_gemm_tc(const int* __restrict__ x_idx,
                                                  const int* __restrict__ dist_label,
                                                  const float* __restrict__ ue,
                                                  const float* __restrict__ ie) {
    extern __shared__ float sm[];
    float* Wsm = sm;
    float* Xsm = sm + 128 * XS;
    int tid = threadIdx.x;
    int r0 = blockIdx.x * 128;

#pragma unroll
    for (int t = 0; t < 16; t++) {
        int i = tid + t * 256;
        int row = i >> 5, q = i & 31;
        float4 v = ((const float4*)g_PG)[row * 32 + q];
        *(float4*)&Wsm[row * XS + q * 4] = v;
    }
#pragma unroll
    for (int t = 0; t < 16; t++) {
        int i = tid + t * 256;
        int row = i >> 5, q = i & 31;
        int r = r0 + row;
        int node = x_idx[r];
        const float* p = (node < N_USERS) ? (ue + (size_t)node * DIM)
                                          : (ie + (size_t)(node - N_USERS) * DIM);
        float4 e4 = ((const float4*)p)[q];
        float4 a4 = ((const float4*)g_aggr)[(size_t)node * 32 + q];
        float4 v = make_float4(e4.x + fmaxf(a4.x, 0.f), e4.y + fmaxf(a4.y, 0.f),
                               e4.z + fmaxf(a4.z, 0.f), e4.w + fmaxf(a4.w, 0.f));
        *(float4*)&Xsm[row * XS + q * 4] = v;
    }
    __syncthreads();

    int warp = tid >> 5, lane = tid & 31;
    int gid = lane >> 2, tig = lane & 3;
    int wr = warp * 16;

    float acc[16][4];
#pragma unroll
    for (int n = 0; n < 16; n++)
#pragma unroll
        for (int m = 0; m < 4; m++) acc[n][m] = 0.f;

#pragma unroll
    for (int k = 0; k < 128; k += 8) {
        unsigned a0 = f2tf32(Xsm[(wr + gid) * XS + k + tig]);
        unsigned a1 = f2tf32(Xsm[(wr + gid + 8) * XS + k + tig]);
        unsigned a2 = f2tf32(Xsm[(wr + gid) * XS + k + tig + 4]);
        unsigned a3 = f2tf32(Xsm[(wr + gid + 8) * XS + k + tig + 4]);
#pragma unroll
        for (int n = 0; n < 16; n++) {
            unsigned b0 = f2tf32(Wsm[(k + tig) * XS + n * 8 + gid]);
            unsigned b1 = f2tf32(Wsm[(k + tig + 4) * XS + n * 8 + gid]);
            mma_tf32(acc[n], a0, a1, a2, a3, b0, b1);
        }
    }

    int row0 = r0 + wr + gid;
    int row1 = row0 + 8;
    int dl0 = dist_label[row0];
    int dl1 = dist_label[row1];
#pragma unroll
    for (int n = 0; n < 16; n++) {
        int c0 = n * 8 + tig * 2;
        float2 dv0 = *(const float2*)&g_D4[dl0 * DIM + c0];
        float2 dv1 = *(const float2*)&g_D4[dl1 * DIM + c0];
        float2 o0 = make_float2(acc[n][0] + dv0.x, acc[n][1] + dv0.y);
        float2 o1 = make_float2(acc[n][2] + dv1.x, acc[n][3] + dv1.y);
        *(float2*)&g_xw[(size_t)row0 * DIM + c0] = o0;
        *(float2*)&g_xw[(size_t)row1 * DIM + c0] = o1;
    }
}

// ---------------- local GCN edge scatter (2 edges/warp) -----------------------
__global__ void __launch_bounds__(256) local_scatter(const int* __restrict__ lsrc,
                                                     const int* __restrict__ ldst) {
    int warp = (blockIdx.x * blockDim.x + threadIdx.x) >> 5;
    int lane = threadIdx.x & 31;
    int e0 = warp * 2;
    if (e0 >= EL) return;
    int e1 = e0 + 1;
    bool has1 = (e1 < EL);

    int s0 = lsrc[e0];
    int s1 = lsrc[has1 ? e1 : e0];
    int d0 = ldst[e0];
    int d1 = ldst[has1 ? e1 : e0];

    float4 v0 = ((const float4*)g_xw)[(size_t)s0 * 32 + lane];
    float4 v1 = ((const float4*)g_xw)[(size_t)s1 * 32 + lane];
    float n0 = g_dinv[s0] * g_dinv[d0];
    float n1 = g_dinv[s1] * g_dinv[d1];

    v0.x *= n0; v0.y *= n0; v0.z *= n0; v0.w *= n0;
    red_add_v4(&g_lout[(size_t)d0 * DIM + lane * 4], v0);
    if (has1) {
        v1.x *= n1; v1.y *= n1; v1.z *= n1; v1.w *= n1;
        red_add_v4(&g_lout[(size_t)d1 * DIM + lane * 4], v1);
    }
}

// ---------------- pool per batch segment + tanh(@pool_w + b) -----------------
__device__ int lower_bound_i(const int* a, int n, int v) {
    int lo = 0, hi = n;
    while (lo < hi) { int m = (lo + hi) >> 1; if (a[m] < v) lo = m + 1; else hi = m; }
    return lo;
}
__global__ void __launch_bounds__(128) pool_kernel(const int* __restrict__ batch,
                                                   const float* __restrict__ gcn_b,
                                                   const float* __restrict__ pool_w,
                                                   const float* __restrict__ pool_b,
                                                   float* __restrict__ out, int out_size) {
    __shared__ int seg[2];
    __shared__ float mean[DIM];
    int b = blockIdx.x;
    int j = threadIdx.x;
    if (j == 0) seg[0] = lower_bound_i(batch, NL, b);
    if (j == 1) seg[1] = lower_bound_i(batch, NL, b + 1);
    __syncthreads();
    int lo = seg[0], hi = seg[1];
    float acc = 0.f;
    for (int i = lo; i < hi; i++) {
        float di = g_dinv[i];
        acc += g_lout[(size_t)i * DIM + j] + di * di * g_xw[(size_t)i * DIM + j];
    }
    int cnt = hi - lo;
    acc += (float)cnt * gcn_b[j];
    mean[j] = (cnt > 0) ? acc / (float)cnt : 0.f;
    __syncthreads();
    float t = pool_b[j];
#pragma unroll 8
    for (int k = 0; k < DIM; k++) t += mean[k] * pool_w[k * DIM + j];
    float h = tanhf(t);
    g_hsub[b * DIM + j] = h;
    if (out_size >= OUT_TOTAL) out[OUT_HSUB + b * DIM + j] = h;
}

// ---------------- final MLP ---------------------------------------------------
__global__ void __launch_bounds__(128) final_kernel(const float* __restrict__ w1,
                                                    const float* __restrict__ b1,
                                                    const float* __restrict__ w2,
                                                    const float* __restrict__ b2,
                                                    float* __restrict__ out) {
    __shared__ float v[4 * DIM];
    __shared__ float hid[64];
    int b = blockIdx.x;
    int j = threadIdx.x;
    v[j]           = g_hsub[b * DIM + j];
    v[DIM + j]     = g_gu[b * DIM + j];
    v[2 * DIM + j] = g_gi[b * DIM + j];
    v[3 * DIM + j] = g_ru[b * DIM + j] * g_rv[b * DIM + j];
    __syncthreads();
    if (j < 64) {
        float a = b1[j];
#pragma unroll 8
        for (int k = 0; k < 4 * DIM; k++) a += v[k] * w1[k * 64 + j];
        hid[j] = fmaxf(a, 0.f) * w2[j];
    }
    __syncthreads();
    if (j == 0) {
        float s = b2[0];
        for (int t = 0; t < 64; t++) s += hid[t];
        out[OUT_PRED + b] = 1.f / (1.f + expf(-s));
    }
}

// ---------------- launch ------------------------------------------------------
extern "C" void kernel_launch(void* const* d_in, const int* in_sizes, int n_in,
                              void* d_out, int out_size) {
    const int*   gei    = (const int*)d_in[0];
    const int*   gea    = (const int*)d_in[1];
    const int*   root_u = (const int*)d_in[2];
    const int*   root_i = (const int*)d_in[3];
    const int*   x_idx  = (const int*)d_in[4];
    const int*   dist_l = (const int*)d_in[5];
    const int*   lei    = (const int*)d_in[6];
    const int*   batch  = (const int*)d_in[7];
    const float* ue     = (const float*)d_in[8];
    const float* ie     = (const float*)d_in[9];
    const float* dist_e = (const float*)d_in[10];
    const float* c_u    = (const float*)d_in[11];
    const float* c_v    = (const float*)d_in[12];
    const float* gnn_W  = (const float*)d_in[13];
    const float* gnn_b  = (const float*)d_in[14];
    const float* sign_e = (const float*)d_in[15];
    const float* iw1    = (const float*)d_in[16];
    const float* ib1    = (const float*)d_in[17];
    const float* iw2    = (const float*)d_in[18];
    const float* ib2    = (const float*)d_in[19];
    const float* lpw    = (const float*)d_in[20];
    const float* lpb    = (const float*)d_in[21];
    const float* gcw    = (const float*)d_in[22];
    const float* gcb    = (const float*)d_in[23];
    const float* pow_   = (const float*)d_in[24];
    const float* pob    = (const float*)d_in[25];
    const float* fw1    = (const float*)d_in[26];
    const float* fb1    = (const float*)d_in[27];
    const float* fw2    = (const float*)d_in[28];
    const float* fb2    = (const float*)d_in[29];
    float* out = (float*)d_out;

    cudaFuncSetAttribute(y_gemm_tc,  cudaFuncAttributeMaxDynamicSharedMemorySize, GEMM_SMEM);
    cudaFuncSetAttribute(xw_gemm_tc, cudaFuncAttributeMaxDynamicSharedMemorySize, GEMM_SMEM);

    init_kernel<<<1184, 256>>>();
    // CSR build for global edges
    hist_kernel<<<(E_G + 255) / 256, 256>>>(gei + E_G);
    scan_a_kernel<<<NSEG, SCAN_B>>>();
    scan_b2_kernel<<<1, 256>>>();
    scan_c_kernel<<<NSEG, SCAN_B>>>();
    fill_kernel<<<(E_G + 255) / 256, 256>>>(gei, gei + E_G, gea);

    pg_kernel<<<257, 128>>>(lpw, lpb, gcw);
    d4_kernel<<<4, 128>>>(dist_e);
    deg_kernel<<<EL / 256, 256>>>(lei + EL);
    dinv_kernel<<<NL / 256, 256>>>();

    y_gemm_tc<<<(N_NODES + 127) / 128, 256, GEMM_SMEM>>>(ue, ie, gnn_W, gnn_b);
    gather_aggr<<<(N_NODES * 32 + 255) / 256, 256>>>(sign_e);

    gugi_kernel<<<(2 * BATCH * 32) / 256, 256>>>(root_u, root_i, ue, ie, out, out_size);
    intent_kernel<<<2 * BATCH, 128>>>(iw1, ib1, iw2, ib2, c_u, c_v, out, out_size);

    xw_gemm_tc<<<NL / 128, 256, GEMM_SMEM>>>(x_idx, dist_l, ue, ie);
    local_scatter<<<(EL / 2) / 8, 256>>>(lei, lei + EL);
    pool_kernel<<<BATCH, 128>>>(batch, gcb, pow_, pob, out, out_size);
    final_kernel<<<BATCH, 128>>>(fw1, fb1, fw2, fb2, out);
}

// round 11
// speedup vs baseline: 1.9151x; 1.0284x over previous
#include <cuda_runtime.h>
#include <math.h>

#define N_USERS   100000
#define N_ITEMS   50000
#define N_NODES   150000
#define DIM       128
#define KINT      8
#define E_G       1500000
#define NL        65536
#define EL        262144
#define BATCH     1024

#define OUT_PRED  0
#define OUT_GU    1024
#define OUT_HSUB  (1024 + 131072)
#define OUT_PU    (1024 + 2*131072)
#define OUT_PV    (1024 + 2*131072 + 8192)
#define OUT_TOTAL (1024 + 2*131072 + 2*8192)

#define XS 132            // padded smem row stride (floats)
#define GEMM_SMEM (2 * 128 * XS * 4)

#define SCAN_B 1024
#define NSEG_G ((N_NODES + SCAN_B - 1) / SCAN_B)   // 147
#define NSEG_L (NL / SCAN_B)                        // 64

// ---------------- scratch (device globals; no allocation allowed) -------------
__device__ float g_Y[N_NODES * DIM];
__device__ float g_aggr[N_NODES * DIM];
__device__ float g_xw[NL * DIM];
__device__ float g_lout[NL * DIM];
__device__ float g_PG[257 * DIM];
__device__ float g_D4[4 * DIM];
__device__ float g_dinv[NL];
__device__ float g_gu[BATCH * DIM];
__device__ float g_gi[BATCH * DIM];
__device__ float g_ru[BATCH * DIM];
__device__ float g_rv[BATCH * DIM];
// CSR scratch: global edges
__device__ int   g_cnt[N_NODES];
__device__ int   g_cur[N_NODES];
__device__ int   g_bsumG[NSEG_G];
__device__ int   g_epack[E_G];       // src | (attr << 24)
// CSR scratch: local edges
__device__ int   g_lcnt[NL];
__device__ int   g_lcur[NL];
__device__ int   g_bsumL[NSEG_L];
__device__ int   g_lpack[EL];        // src

__device__ __forceinline__ unsigned f2tf32(float f) {
    unsigned r;
    asm("cvt.rna.tf32.f32 %0, %1;" : "=r"(r) : "f"(f));
    return r;
}
__device__ __forceinline__ void mma_tf32(float c[4], unsigned a0, unsigned a1,
                                         unsigned a2, unsigned a3,
                                         unsigned b0, unsigned b1) {
    asm volatile("mma.sync.aligned.m16n8k8.row.col.f32.tf32.tf32.f32 "
                 "{%0,%1,%2,%3}, {%4,%5,%6,%7}, {%8,%9}, {%0,%1,%2,%3};"
                 : "+f"(c[0]), "+f"(c[1]), "+f"(c[2]), "+f"(c[3])
                 : "r"(a0), "r"(a1), "r"(a2), "r"(a3), "r"(b0), "r"(b1));
}

// ---------------- init: zero both histograms ----------------------------------
__global__ void init_cnt_kernel() {
    int i = blockIdx.x * blockDim.x + threadIdx.x;
    int stride = gridDim.x * blockDim.x;
    for (int k = i; k < N_NODES; k += stride) g_cnt[k] = 0;
    for (int k = i; k < NL; k += stride) g_lcnt[k] = 0;
}

// ---------------- merged histogram: global + local edges ----------------------
__global__ void hist_both(const int* __restrict__ gdst, const int* __restrict__ ldst) {
    int e = blockIdx.x * blockDim.x + threadIdx.x;
    if (e < E_G) {
        atomicAdd(&g_cnt[gdst[e]], 1);
    } else if (e < E_G + EL) {
        atomicAdd(&g_lcnt[ldst[e - E_G]], 1);
    }
}

// ---------------- merged scan pass A (per-segment sums) -----------------------
__global__ void __launch_bounds__(SCAN_B) scan_a_both() {
    __shared__ int sh[SCAN_B];
    int blk = blockIdx.x;
    const int* cnt; int n; int* bsum; int seg;
    if (blk < NSEG_G) { cnt = g_cnt;  n = N_NODES; bsum = g_bsumG; seg = blk; }
    else              { cnt = g_lcnt; n = NL;      bsum = g_bsumL; seg = blk - NSEG_G; }
    int tid = threadIdx.x;
    int i = seg * SCAN_B + tid;
    sh[tid] = (i < n) ? cnt[i] : 0;
    __syncthreads();
    for (int s = SCAN_B / 2; s > 0; s >>= 1) {
        if (tid < s) sh[tid] += sh[tid + s];
        __syncthreads();
    }
    if (tid == 0) bsum[seg] = sh[0];
}

// ---------------- merged scan pass B (exclusive over segment sums) ------------
__global__ void __launch_bounds__(256) scan_b_both() {
    __shared__ int sh[256];
    int* bsum; int nseg;
    if (blockIdx.x == 0) { bsum = g_bsumG; nseg = NSEG_G; }
    else                 { bsum = g_bsumL; nseg = NSEG_L; }
    int tid = threadIdx.x;
    int v = (tid < nseg) ? bsum[tid] : 0;
    sh[tid] = v;
    __syncthreads();
    for (int ofs = 1; ofs < 256; ofs <<= 1) {
        int t = (tid >= ofs) ? sh[tid - ofs] : 0;
        __syncthreads();
        sh[tid] += t;
        __syncthreads();
    }
    if (tid < nseg) bsum[tid] = sh[tid] - v;   // exclusive
}

// ---------------- merged scan pass C (offsets; local also computes dinv) ------
__global__ void __launch_bounds__(SCAN_B) scan_c_both() {
    __shared__ int sh[SCAN_B];
    int blk = blockIdx.x;
    int tid = threadIdx.x;
    bool isLocal = (blk >= NSEG_G);
    int* cnt; int* cur; int n; const int* bsum; int seg;
    if (!isLocal) { cnt = g_cnt;  cur = g_cur;  n = N_NODES; bsum = g_bsumG; seg = blk; }
    else          { cnt = g_lcnt; cur = g_lcur; n = NL;      bsum = g_bsumL; seg = blk - NSEG_G; }
    int i = seg * SCAN_B + tid;
    int v = (i < n) ? cnt[i] : 0;
    sh[tid] = v;
    __syncthreads();
    for (int ofs = 1; ofs < SCAN_B; ofs <<= 1) {
        int t = (tid >= ofs) ? sh[tid - ofs] : 0;
        __syncthreads();
        sh[tid] += t;
        __syncthreads();
    }
    if (i < n) {
        int excl = sh[tid] - v + bsum[seg];
        cnt[i] = excl;
        cur[i] = excl;
        if (isLocal) g_dinv[i] = rsqrtf((float)(v + 1));  // deg = in-edges + self loop
    }
}

// ---------------- merged fill: global + local ---------------------------------
__global__ void fill_both(const int* __restrict__ gsrc, const int* __restrict__ gdst,
                          const int* __restrict__ attr,
                          const int* __restrict__ lsrc, const int* __restrict__ ldst) {
    int e = blockIdx.x * blockDim.x + threadIdx.x;
    if (e < E_G) {
        int pos = atomicAdd(&g_cur[gdst[e]], 1);
        g_epack[pos] = gsrc[e] | (attr[e] << 24);
    } else if (e < E_G + EL) {
        int le = e - E_G;
        int pos = atomicAdd(&g_lcur[ldst[le]], 1);
        g_lpack[pos] = lsrc[le];
    }
}

// ---------------- Y = all_emb @ W + b  (tf32 tensor-core GEMM) ---------------
__global__ void __launch_bounds__(256) y_gemm_tc(const float* __restrict__ ue,
                                                 const float* __restrict__ ie,
                                                 const float* __restrict__ W,
                                                 const float* __restrict__ bias) {
    extern __shared__ float sm[];
    float* Wsm = sm;
    float* Xsm = sm + 128 * XS;
    int tid = threadIdx.x;
    int r0 = blockIdx.x * 128;

#pragma unroll
    for (int t = 0; t < 16; t++) {
        int i = tid + t * 256;
        int row = i >> 5, q = i & 31;
        float4 v = ((const float4*)W)[row * 32 + q];
        *(float4*)&Wsm[row * XS + q * 4] = v;
    }
#pragma unroll
    for (int t = 0; t < 16; t++) {
        int i = tid + t * 256;
        int row = i >> 5, q = i & 31;
        int r = r0 + row;
        float4 v = make_float4(0.f, 0.f, 0.f, 0.f);
        if (r < N_NODES) {
            const float* p = (r < N_USERS) ? (ue + (size_t)r * DIM)
                                           : (ie + (size_t)(r - N_USERS) * DIM);
            v = ((const float4*)p)[q];
        }
        *(float4*)&Xsm[row * XS + q * 4] = v;
    }
    __syncthreads();

    int warp = tid >> 5, lane = tid & 31;
    int gid = lane >> 2, tig = lane & 3;
    int wr = warp * 16;

    float acc[16][4];
#pragma unroll
    for (int n = 0; n < 16; n++)
#pragma unroll
        for (int m = 0; m < 4; m++) acc[n][m] = 0.f;

#pragma unroll
    for (int k = 0; k < 128; k += 8) {
        unsigned a0 = f2tf32(Xsm[(wr + gid) * XS + k + tig]);
        unsigned a1 = f2tf32(Xsm[(wr + gid + 8) * XS + k + tig]);
        unsigned a2 = f2tf32(Xsm[(wr + gid) * XS + k + tig + 4]);
        unsigned a3 = f2tf32(Xsm[(wr + gid + 8) * XS + k + tig + 4]);
#pragma unroll
        for (int n = 0; n < 16; n++) {
            unsigned b0 = f2tf32(Wsm[(k + tig) * XS + n * 8 + gid]);
            unsigned b1 = f2tf32(Wsm[(k + tig + 4) * XS + n * 8 + gid]);
            mma_tf32(acc[n], a0, a1, a2, a3, b0, b1);
        }
    }

    int row0 = r0 + wr + gid;
    int row1 = row0 + 8;
#pragma unroll
    for (int n = 0; n < 16; n++) {
        int c0 = n * 8 + tig * 2;
        float bx = bias[c0], by = bias[c0 + 1];
        if (row0 < N_NODES) {
            float2 o = make_float2(acc[n][0] + bx, acc[n][1] + by);
            *(float2*)&g_Y[(size_t)row0 * DIM + c0] = o;
        }
        if (row1 < N_NODES) {
            float2 o = make_float2(acc[n][2] + bx, acc[n][3] + by);
            *(float2*)&g_Y[(size_t)row1 * DIM + c0] = o;
        }
    }
}

// ---------------- aggr[d] = sum over in-edges of sign * Y[src]  (gather) -----
__global__ void __launch_bounds__(256) gather_aggr(const float* __restrict__ sign_emb) {
    int warp = (blockIdx.x * blockDim.x + threadIdx.x) >> 5;
    int lane = threadIdx.x & 31;
    if (warp >= N_NODES) return;
    float sA = __ldg(sign_emb);
    float sB = __ldg(sign_emb + 1);
    int p   = g_cnt[warp];
    int end = g_cur[warp];
    float4 acc = make_float4(0.f, 0.f, 0.f, 0.f);
    for (; p + 1 < end; p += 2) {
        int pk0 = g_epack[p];
        int pk1 = g_epack[p + 1];
        int s0 = pk0 & 0xFFFFFF;
        int s1 = pk1 & 0xFFFFFF;
        float4 v0 = ((const float4*)g_Y)[(size_t)s0 * 32 + lane];
        float4 v1 = ((const float4*)g_Y)[(size_t)s1 * 32 + lane];
        float sg0 = (pk0 >> 24) ? sB : sA;
        float sg1 = (pk1 >> 24) ? sB : sA;
        acc.x += sg0 * v0.x + sg1 * v1.x;
        acc.y += sg0 * v0.y + sg1 * v1.y;
        acc.z += sg0 * v0.z + sg1 * v1.z;
        acc.w += sg0 * v0.w + sg1 * v1.w;
    }
    if (p < end) {
        int pk = g_epack[p];
        int s = pk & 0xFFFFFF;
        float sg = (pk >> 24) ? sB : sA;
        float4 v = ((const float4*)g_Y)[(size_t)s * 32 + lane];
        acc.x += sg * v.x; acc.y += sg * v.y; acc.z += sg * v.z; acc.w += sg * v.w;
    }
    ((float4*)g_aggr)[(size_t)warp * 32 + lane] = acc;
}

// ---------------- intent heads (gugi folded in) -------------------------------
__global__ void __launch_bounds__(128) intent_kernel(const int* __restrict__ root_u,
                                                     const int* __restrict__ root_i,
                                                     const float* __restrict__ ue,
                                                     const float* __restrict__ ie,
                                                     const float* __restrict__ w1,
                                                     const float* __restrict__ b1,
                                                     const float* __restrict__ w2,
                                                     const float* __restrict__ b2,
                                                     const float* __restrict__ c_u,
                                                     const float* __restrict__ c_v,
                                                     float* __restrict__ out, int out_size) {
    __shared__ float xs[DIM];
    __shared__ float h1[DIM];
    __shared__ float lg[KINT];
    __shared__ float ps[KINT];
    int side = blockIdx.x >> 10;
    int b = blockIdx.x & 1023;
    int j = threadIdx.x;

    // fold of gugi: repr = emb + relu(aggr)
    int node = side ? (root_i[b] + N_USERS) : root_u[b];
    const float* emb = (node < N_USERS) ? (ue + (size_t)node * DIM)
                                        : (ie + (size_t)(node - N_USERS) * DIM);
    float ev = emb[j];
    float av = g_aggr[(size_t)node * DIM + j];
    float r0 = ev + fmaxf(av, 0.f);
    xs[j] = r0;
    (side ? g_gi : g_gu)[b * DIM + j] = r0;
    if (!side && out_size >= OUT_TOTAL) out[OUT_GU + b * DIM + j] = r0;
    __syncthreads();

    float a = b1[j];
#pragma unroll 8
    for (int k = 0; k < DIM; k++) a += xs[k] * w1[k * DIM + j];
    h1[j] = tanhf(a);
    __syncthreads();
    if (j < KINT) {
        float l = b2[j];
        for (int k = 0; k < DIM; k++) l += h1[k] * w2[k * KINT + j];
        lg[j] = l;
    }
    __syncthreads();
    if (j == 0) {
        float m = lg[0];
        for (int t = 1; t < KINT; t++) m = fmaxf(m, lg[t]);
        float s = 0.f;
        for (int t = 0; t < KINT; t++) { ps[t] = expf(lg[t] - m); s += ps[t]; }
        float inv = 1.f / s;
        for (int t = 0; t < KINT; t++) ps[t] *= inv;
    }
    __syncthreads();
    const float* proto = side ? c_v : c_u;
    float r = 0.f;
#pragma unroll
    for (int t = 0; t < KINT; t++) r += ps[t] * proto[t * DIM + j];
    (side ? g_rv : g_ru)[b * DIM + j] = r;
    if (j < KINT && out_size >= OUT_TOTAL)
        out[(side ? OUT_PV : OUT_PU) + b * KINT + j] = ps[j];
}

// ---------------- PG = local_proj_w @ gcn_w ----------------------------------
__global__ void __launch_bounds__(128) pg_kernel(const float* __restrict__ P,
                                                 const float* __restrict__ Pb,
                                                 const float* __restrict__ G) {
    __shared__ float prow[DIM];
    int m = blockIdx.x;
    int j = threadIdx.x;
    prow[j] = (m < 256) ? P[m * DIM + j] : Pb[j];
    __syncthreads();
    float a = 0.f;
#pragma unroll 8
    for (int k = 0; k < DIM; k++) a += prow[k] * G[k * DIM + j];
    g_PG[m * DIM + j] = a;
}

__global__ void __launch_bounds__(128) d4_kernel(const float* __restrict__ dist_emb) {
    __shared__ float de[DIM];
    int d = blockIdx.x;
    int j = threadIdx.x;
    de[j] = dist_emb[d * DIM + j];
    __syncthreads();
    float a = g_PG[256 * DIM + j];
#pragma unroll 8
    for (int k = 0; k < DIM; k++) a += de[k] * g_PG[(128 + k) * DIM + j];
    g_D4[d * DIM + j] = a;
}

// ---------------- xw = repr(x_idx) @ PG_top + D4[dist_label]  (tf32 TC) ------
__global__ void __launch_bounds__(256) xw_gemm_tc(const int* __restrict__ x_idx,
                                                  const int* __restrict__ dist_label,
                                                  const float* __restrict__ ue,
                                                  const float* __restrict__ ie) {
    extern __shared__ float sm[];
    float* Wsm = sm;
    float* Xsm = sm + 128 * XS;
    int tid = threadIdx.x;
    int r0 = blockIdx.x * 128;

#pragma unroll
    for (int t = 0; t < 16; t++) {
        int i = tid + t * 256;
        int row = i >> 5, q = i & 31;
        float4 v = ((const float4*)g_PG)[row * 32 + q];
        *(float4*)&Wsm[row * XS + q * 4] = v;
    }
#pragma unroll
    for (int t = 0; t < 16; t++) {
        int i = tid + t * 256;
        int row = i >> 5, q = i & 31;
        int r = r0 + row;
        int node = x_idx[r];
        const float* p = (node < N_USERS) ? (ue + (size_t)node * DIM)
                                          : (ie + (size_t)(node - N_USERS) * DIM);
        float4 e4 = ((const float4*)p)[q];
        float4 a4 = ((const float4*)g_aggr)[(size_t)node * 32 + q];
        float4 v = make_float4(e4.x + fmaxf(a4.x, 0.f), e4.y + fmaxf(a4.y, 0.f),
                               e4.z + fmaxf(a4.z, 0.f), e4.w + fmaxf(a4.w, 0.f));
        *(float4*)&Xsm[row * XS + q * 4] = v;
    }
    __syncthreads();

    int warp = tid >> 5, lane = tid & 31;
    int gid = lane >> 2, tig = lane & 3;
    int wr = warp * 16;

    float acc[16][4];
#pragma unroll
    for (int n = 0; n < 16; n++)
#pragma unroll
        for (int m = 0; m < 4; m++) acc[n][m] = 0.f;

#pragma unroll
    for (int k = 0; k < 128; k += 8) {
        unsigned a0 = f2tf32(Xsm[(wr + gid) * XS + k + tig]);
        unsigned a1 = f2tf32(Xsm[(wr + gid + 8) * XS + k + tig]);
        unsigned a2 = f2tf32(Xsm[(wr + gid) * XS + k + tig + 4]);
        unsigned a3 = f2tf32(Xsm[(wr + gid + 8) * XS + k + tig + 4]);
#pragma unroll
        for (int n = 0; n < 16; n++) {
            unsigned b0 = f2tf32(Wsm[(k + tig) * XS + n * 8 + gid]);
            unsigned b1 = f2tf32(Wsm[(k + tig + 4) * XS + n * 8 + gid]);
            mma_tf32(acc[n], a0, a1, a2, a3, b0, b1);
        }
    }

    int row0 = r0 + wr + gid;
    int row1 = row0 + 8;
    int dl0 = dist_label[row0];
    int dl1 = dist_label[row1];
#pragma unroll
    for (int n = 0; n < 16; n++) {
        int c0 = n * 8 + tig * 2;
        float2 dv0 = *(const float2*)&g_D4[dl0 * DIM + c0];
        float2 dv1 = *(const float2*)&g_D4[dl1 * DIM + c0];
        float2 o0 = make_float2(acc[n][0] + dv0.x, acc[n][1] + dv0.y);
        float2 o1 = make_float2(acc[n][2] + dv1.x, acc[n][3] + dv1.y);
        *(float2*)&g_xw[(size_t)row0 * DIM + c0] = o0;
        *(float2*)&g_xw[(size_t)row1 * DIM + c0] = o1;
    }
}

// ---------------- local GCN gather: lout[d] = dinv[d]*(Σ dinv[s]xw[s] + dinv[d]xw[d])
__global__ void __launch_bounds__(256) lgather_kernel() {
    int warp = (blockIdx.x * blockDim.x + threadIdx.x) >> 5;
    int lane = threadIdx.x & 31;
    if (warp >= NL) return;
    int p   = g_lcnt[warp];
    int end = g_lcur[warp];
    float dd = g_dinv[warp];
    float4 sv = ((const float4*)g_xw)[(size_t)warp * 32 + lane];
    float4 acc = make_float4(dd * sv.x, dd * sv.y, dd * sv.z, dd * sv.w);  // self loop
    for (; p + 1 < end; p += 2) {
        int s0 = g_lpack[p];
        int s1 = g_lpack[p + 1];
        float4 v0 = ((const float4*)g_xw)[(size_t)s0 * 32 + lane];
        float4 v1 = ((const float4*)g_xw)[(size_t)s1 * 32 + lane];
        float n0 = g_dinv[s0];
        float n1 = g_dinv[s1];
        acc.x += n0 * v0.x + n1 * v1.x;
        acc.y += n0 * v0.y + n1 * v1.y;
        acc.z += n0 * v0.z + n1 * v1.z;
        acc.w += n0 * v0.w + n1 * v1.w;
    }
    if (p < end) {
        int s = g_lpack[p];
        float4 v = ((const float4*)g_xw)[(size_t)s * 32 + lane];
        float n = g_dinv[s];
        acc.x += n * v.x; acc.y += n * v.y; acc.z += n * v.z; acc.w += n * v.w;
    }
    acc.x *= dd; acc.y *= dd; acc.z *= dd; acc.w *= dd;
    ((float4*)g_lout)[(size_t)warp * 32 + lane] = acc;
}

// ---------------- pool + final MLP fused (same block index b) -----------------
__device__ int lower_bound_i(const int* a, int n, int v) {
    int lo = 0, hi = n;
    while (lo < hi) { int m = (lo + hi) >> 1; if (a[m] < v) lo = m + 1; else hi = m; }
    return lo;
}
__global__ void __launch_bounds__(128) pool_final_kernel(const int* __restrict__ batch,
                                                         const float* __restrict__ gcn_b,
                                                         const float* __restrict__ pool_w,
                                                         const float* __restrict__ pool_b,
                                                         const float* __restrict__ w1,
                                                         const float* __restrict__ b1,
                                                         const float* __restrict__ w2,
                                                         const float* __restrict__ b2,
                                                         float* __restrict__ out, int out_size) {
    __shared__ int seg[2];
    __shared__ float mean[DIM];
    __shared__ float v[4 * DIM];
    __shared__ float hid[64];
    int b = blockIdx.x;
    int j = threadIdx.x;
    if (j == 0) seg[0] = lower_bound_i(batch, NL, b);
    if (j == 1) seg[1] = lower_bound_i(batch, NL, b + 1);
    __syncthreads();
    int lo = seg[0], hi = seg[1];
    float acc = 0.f;
    for (int i = lo; i < hi; i++)
        acc += g_lout[(size_t)i * DIM + j];
    int cnt = hi - lo;
    mean[j] = (cnt > 0) ? (acc / (float)cnt + gcn_b[j]) : 0.f;
    __syncthreads();
    float t = pool_b[j];
#pragma unroll 8
    for (int k = 0; k < DIM; k++) t += mean[k] * pool_w[k * DIM + j];
    float h = tanhf(t);
    if (out_size >= OUT_TOTAL) out[OUT_HSUB + b * DIM + j] = h;

    // final MLP for this b (hsub stays in smem)
    v[j]           = h;
    v[DIM + j]     = g_gu[b * DIM + j];
    v[2 * DIM + j] = g_gi[b * DIM + j];
    v[3 * DIM + j] = g_ru[b * DIM + j] * g_rv[b * DIM + j];
    __syncthreads();
    if (j < 64) {
        float a = b1[j];
#pragma unroll 8
        for (int k = 0; k < 4 * DIM; k++) a += v[k] * w1[k * 64 + j];
        hid[j] = fmaxf(a, 0.f) * w2[j];
    }
    __syncthreads();
    if (j == 0) {
        float s = b2[0];
        for (int tte = 0; tte < 64; tte++) s += hid[tte];
        out[OUT_PRED + b] = 1.f / (1.f + expf(-s));
    }
}

// ---------------- launch (single default stream, like passing rounds 3-5) -----
extern "C" void kernel_launch(void* const* d_in, const int* in_sizes, int n_in,
                              void* d_out, int out_size) {
    const int*   gei    = (const int*)d_in[0];
    const int*   gea    = (const int*)d_in[1];
    const int*   root_u = (const int*)d_in[2];
    const int*   root_i = (const int*)d_in[3];
    const int*   x_idx  = (const int*)d_in[4];
    const int*   dist_l = (const int*)d_in[5];
    const int*   lei    = (const int*)d_in[6];
    const int*   batch  = (const int*)d_in[7];
    const float* ue     = (const float*)d_in[8];
    const float* ie     = (const float*)d_in[9];
    const float* dist_e = (const float*)d_in[10];
    const float* c_u    = (const float*)d_in[11];
    const float* c_v    = (const float*)d_in[12];
    const float* gnn_W  = (const float*)d_in[13];
    const float* gnn_b  = (const float*)d_in[14];
    const float* sign_e = (const float*)d_in[15];
    const float* iw1    = (const float*)d_in[16];
    const float* ib1    = (const float*)d_in[17];
    const float* iw2    = (const float*)d_in[18];
    const float* ib2    = (const float*)d_in[19];
    const float* lpw    = (const float*)d_in[20];
    const float* lpb    = (const float*)d_in[21];
    const float* gcw    = (const float*)d_in[22];
    const float* gcb    = (const float*)d_in[23];
    const float* pow_   = (const float*)d_in[24];
    const float* pob    = (const float*)d_in[25];
    const float* fw1    = (const float*)d_in[26];
    const float* fb1    = (const float*)d_in[27];
    const float* fw2    = (const float*)d_in[28];
    const float* fb2    = (const float*)d_in[29];
    float* out = (float*)d_out;

    cudaFuncSetAttribute(y_gemm_tc,  cudaFuncAttributeMaxDynamicSharedMemorySize, GEMM_SMEM);
    cudaFuncSetAttribute(xw_gemm_tc, cudaFuncAttributeMaxDynamicSharedMemorySize, GEMM_SMEM);

    init_cnt_kernel<<<592, 256>>>();
    hist_both<<<(E_G + EL + 255) / 256, 256>>>(gei + E_G, lei + EL);
    scan_a_both<<<NSEG_G + NSEG_L, SCAN_B>>>();
    scan_b_both<<<2, 256>>>();
    scan_c_both<<<NSEG_G + NSEG_L, SCAN_B>>>();
    fill_both<<<(E_G + EL + 255) / 256, 256>>>(gei, gei + E_G, gea, lei, lei + EL);

    y_gemm_tc<<<(N_NODES + 127) / 128, 256, GEMM_SMEM>>>(ue, ie, gnn_W, gnn_b);
    gather_aggr<<<(N_NODES * 32 + 255) / 256, 256>>>(sign_e);

    intent_kernel<<<2 * BATCH, 128>>>(root_u, root_i, ue, ie,
                                      iw1, ib1, iw2, ib2, c_u, c_v, out, out_size);

    pg_kernel<<<257, 128>>>(lpw, lpb, gcw);
    d4_kernel<<<4, 128>>>(dist_e);
    xw_gemm_tc<<<NL / 128, 256, GEMM_SMEM>>>(x_idx, dist_l, ue, ie);

    lgather_kernel<<<(NL * 32) / 256, 256>>>();
    pool_final_kernel<<<BATCH, 128>>>(batch, gcb, pow_, pob,
                                      fw1, fb1, fw2, fb2, out, out_size);
}

// round 13
// speedup vs baseline: 1.9808x; 1.0343x over previous
#include <cuda_runtime.h>
#include <math.h>

#define N_USERS   100000
#define N_ITEMS   50000
#define N_NODES   150000
#define DIM       128
#define KINT      8
#define E_G       1500000
#define NL        65536
#define EL        262144
#define BATCH     1024

#define OUT_PRED  0
#define OUT_GU    1024
#define OUT_HSUB  (1024 + 131072)
#define OUT_PU    (1024 + 2*131072)
#define OUT_PV    (1024 + 2*131072 + 8192)
#define OUT_TOTAL (1024 + 2*131072 + 2*8192)

#define XS 132            // padded smem row stride (floats)
#define GEMM_SMEM (2 * 128 * XS * 4)

#define SCAN_B 1024
#define NSEG_G ((N_NODES + SCAN_B - 1) / SCAN_B)   // 147
#define NSEG_L (NL / SCAN_B)                        // 64

// ---------------- scratch (device globals; no allocation allowed) -------------
__device__ float g_Y[N_NODES * DIM];
__device__ float g_aggr[N_NODES * DIM];
__device__ float g_xw[NL * DIM];
__device__ float g_lout[NL * DIM];
__device__ float g_PG[257 * DIM];
__device__ float g_D4[4 * DIM];
__device__ float g_dinv[NL];
__device__ float g_gu[BATCH * DIM];
__device__ float g_gi[BATCH * DIM];
__device__ float g_ru[BATCH * DIM];
__device__ float g_rv[BATCH * DIM];
// CSR scratch: global edges
__device__ int   g_cnt[N_NODES];
__device__ int   g_cur[N_NODES];
__device__ int   g_bsumG[NSEG_G];
__device__ int   g_epack[E_G];       // src | (attr << 24)
// CSR scratch: local edges
__device__ int   g_lcnt[NL];
__device__ int   g_lcur[NL];
__device__ int   g_bsumL[NSEG_L];
__device__ int   g_lpack[EL];        // src

__device__ __forceinline__ unsigned f2tf32(float f) {
    unsigned r;
    asm("cvt.rna.tf32.f32 %0, %1;" : "=r"(r) : "f"(f));
    return r;
}
__device__ __forceinline__ void mma_tf32(float c[4], unsigned a0, unsigned a1,
                                         unsigned a2, unsigned a3,
                                         unsigned b0, unsigned b1) {
    asm volatile("mma.sync.aligned.m16n8k8.row.col.f32.tf32.tf32.f32 "
                 "{%0,%1,%2,%3}, {%4,%5,%6,%7}, {%8,%9}, {%0,%1,%2,%3};"
                 : "+f"(c[0]), "+f"(c[1]), "+f"(c[2]), "+f"(c[3])
                 : "r"(a0), "r"(a1), "r"(a2), "r"(a3), "r"(b0), "r"(b1));
}

// ---------------- init: zero both histograms ----------------------------------
__global__ void init_cnt_kernel() {
    int i = blockIdx.x * blockDim.x + threadIdx.x;
    int stride = gridDim.x * blockDim.x;
    for (int k = i; k < N_NODES; k += stride) g_cnt[k] = 0;
    for (int k = i; k < NL; k += stride) g_lcnt[k] = 0;
}

// ---------------- merged histogram: global + local edges ----------------------
__global__ void hist_both(const int* __restrict__ gdst, const int* __restrict__ ldst) {
    int e = blockIdx.x * blockDim.x + threadIdx.x;
    if (e < E_G) {
        atomicAdd(&g_cnt[gdst[e]], 1);
    } else if (e < E_G + EL) {
        atomicAdd(&g_lcnt[ldst[e - E_G]], 1);
    }
}

// ---------------- merged scan pass A (per-segment sums) -----------------------
__global__ void __launch_bounds__(SCAN_B) scan_a_both() {
    __shared__ int sh[SCAN_B];
    int blk = blockIdx.x;
    const int* cnt; int n; int* bsum; int seg;
    if (blk < NSEG_G) { cnt = g_cnt;  n = N_NODES; bsum = g_bsumG; seg = blk; }
    else              { cnt = g_lcnt; n = NL;      bsum = g_bsumL; seg = blk - NSEG_G; }
    int tid = threadIdx.x;
    int i = seg * SCAN_B + tid;
    sh[tid] = (i < n) ? cnt[i] : 0;
    __syncthreads();
    for (int s = SCAN_B / 2; s > 0; s >>= 1) {
        if (tid < s) sh[tid] += sh[tid + s];
        __syncthreads();
    }
    if (tid == 0) bsum[seg] = sh[0];
}

// ---------------- scan pass C (base from segment sums + in-block prefix) ------
// scan_b is folded in: each block reduces bsum[0..seg) for its base.
__global__ void __launch_bounds__(SCAN_B) scan_c_both() {
    __shared__ int sh[SCAN_B];
    __shared__ int baseSh;
    int blk = blockIdx.x;
    int tid = threadIdx.x;
    bool isLocal = (blk >= NSEG_G);
    int* cnt; int* cur; int n; const int* bsum; int seg;
    if (!isLocal) { cnt = g_cnt;  cur = g_cur;  n = N_NODES; bsum = g_bsumG; seg = blk; }
    else          { cnt = g_lcnt; cur = g_lcur; n = NL;      bsum = g_bsumL; seg = blk - NSEG_G; }

    // base = sum of prior segments' totals
    sh[tid] = (tid < seg) ? bsum[tid] : 0;     // seg <= 147 < SCAN_B
    __syncthreads();
    for (int s = SCAN_B / 2; s > 0; s >>= 1) {
        if (tid < s) sh[tid] += sh[tid + s];
        __syncthreads();
    }
    if (tid == 0) baseSh = sh[0];
    __syncthreads();
    int base = baseSh;
    __syncthreads();

    // inclusive prefix over this segment's counts
    int i = seg * SCAN_B + tid;
    int v = (i < n) ? cnt[i] : 0;
    sh[tid] = v;
    __syncthreads();
    for (int ofs = 1; ofs < SCAN_B; ofs <<= 1) {
        int t = (tid >= ofs) ? sh[tid - ofs] : 0;
        __syncthreads();
        sh[tid] += t;
        __syncthreads();
    }
    if (i < n) {
        int excl = sh[tid] - v + base;
        cnt[i] = excl;
        cur[i] = excl;
        if (isLocal) g_dinv[i] = rsqrtf((float)(v + 1));  // deg = in-edges + self loop
    }
}

// ---------------- merged fill: global + local ---------------------------------
__global__ void fill_both(const int* __restrict__ gsrc, const int* __restrict__ gdst,
                          const int* __restrict__ attr,
                          const int* __restrict__ lsrc, const int* __restrict__ ldst) {
    int e = blockIdx.x * blockDim.x + threadIdx.x;
    if (e < E_G) {
        int pos = atomicAdd(&g_cur[gdst[e]], 1);
        g_epack[pos] = gsrc[e] | (attr[e] << 24);
    } else if (e < E_G + EL) {
        int le = e - E_G;
        int pos = atomicAdd(&g_lcur[ldst[le]], 1);
        g_lpack[pos] = lsrc[le];
    }
}

// ---------------- Y = all_emb @ W + b  (tf32 tensor-core GEMM) ---------------
__global__ void __launch_bounds__(256) y_gemm_tc(const float* __restrict__ ue,
                                                 const float* __restrict__ ie,
                                                 const float* __restrict__ W,
                                                 const float* __restrict__ bias) {
    extern __shared__ float sm[];
    float* Wsm = sm;
    float* Xsm = sm + 128 * XS;
    int tid = threadIdx.x;
    int r0 = blockIdx.x * 128;

#pragma unroll
    for (int t = 0; t < 16; t++) {
        int i = tid + t * 256;
        int row = i >> 5, q = i & 31;
        float4 v = ((const float4*)W)[row * 32 + q];
        *(float4*)&Wsm[row * XS + q * 4] = v;
    }
#pragma unroll
    for (int t = 0; t < 16; t++) {
        int i = tid + t * 256;
        int row = i >> 5, q = i & 31;
        int r = r0 + row;
        float4 v = make_float4(0.f, 0.f, 0.f, 0.f);
        if (r < N_NODES) {
            const float* p = (r < N_USERS) ? (ue + (size_t)r * DIM)
                                           : (ie + (size_t)(r - N_USERS) * DIM);
            v = ((const float4*)p)[q];
        }
        *(float4*)&Xsm[row * XS + q * 4] = v;
    }
    __syncthreads();

    int warp = tid >> 5, lane = tid & 31;
    int gid = lane >> 2, tig = lane & 3;
    int wr = warp * 16;

    float acc[16][4];
#pragma unroll
    for (int n = 0; n < 16; n++)
#pragma unroll
        for (int m = 0; m < 4; m++) acc[n][m] = 0.f;

#pragma unroll
    for (int k = 0; k < 128; k += 8) {
        unsigned a0 = f2tf32(Xsm[(wr + gid) * XS + k + tig]);
        unsigned a1 = f2tf32(Xsm[(wr + gid + 8) * XS + k + tig]);
        unsigned a2 = f2tf32(Xsm[(wr + gid) * XS + k + tig + 4]);
        unsigned a3 = f2tf32(Xsm[(wr + gid + 8) * XS + k + tig + 4]);
#pragma unroll
        for (int n = 0; n < 16; n++) {
            unsigned b0 = f2tf32(Wsm[(k + tig) * XS + n * 8 + gid]);
            unsigned b1 = f2tf32(Wsm[(k + tig + 4) * XS + n * 8 + gid]);
            mma_tf32(acc[n], a0, a1, a2, a3, b0, b1);
        }
    }

    int row0 = r0 + wr + gid;
    int row1 = row0 + 8;
#pragma unroll
    for (int n = 0; n < 16; n++) {
        int c0 = n * 8 + tig * 2;
        float bx = bias[c0], by = bias[c0 + 1];
        if (row0 < N_NODES) {
            float2 o = make_float2(acc[n][0] + bx, acc[n][1] + by);
            *(float2*)&g_Y[(size_t)row0 * DIM + c0] = o;
        }
        if (row1 < N_NODES) {
            float2 o = make_float2(acc[n][2] + bx, acc[n][3] + by);
            *(float2*)&g_Y[(size_t)row1 * DIM + c0] = o;
        }
    }
}

// ---------------- aggr[d] = sum over in-edges of sign * Y[src]  (gather) -----
__global__ void __launch_bounds__(256) gather_aggr(const float* __restrict__ sign_emb) {
    int warp = (blockIdx.x * blockDim.x + threadIdx.x) >> 5;
    int lane = threadIdx.x & 31;
    if (warp >= N_NODES) return;
    float sA = __ldg(sign_emb);
    float sB = __ldg(sign_emb + 1);
    int p   = g_cnt[warp];
    int end = g_cur[warp];
    float4 acc = make_float4(0.f, 0.f, 0.f, 0.f);
    for (; p + 1 < end; p += 2) {
        int pk0 = g_epack[p];
        int pk1 = g_epack[p + 1];
        int s0 = pk0 & 0xFFFFFF;
        int s1 = pk1 & 0xFFFFFF;
        float4 v0 = ((const float4*)g_Y)[(size_t)s0 * 32 + lane];
        float4 v1 = ((const float4*)g_Y)[(size_t)s1 * 32 + lane];
        float sg0 = (pk0 >> 24) ? sB : sA;
        float sg1 = (pk1 >> 24) ? sB : sA;
        acc.x += sg0 * v0.x + sg1 * v1.x;
        acc.y += sg0 * v0.y + sg1 * v1.y;
        acc.z += sg0 * v0.z + sg1 * v1.z;
        acc.w += sg0 * v0.w + sg1 * v1.w;
    }
    if (p < end) {
        int pk = g_epack[p];
        int s = pk & 0xFFFFFF;
        float sg = (pk >> 24) ? sB : sA;
        float4 v = ((const float4*)g_Y)[(size_t)s * 32 + lane];
        acc.x += sg * v.x; acc.y += sg * v.y; acc.z += sg * v.z; acc.w += sg * v.w;
    }
    ((float4*)g_aggr)[(size_t)warp * 32 + lane] = acc;
}

// ---------------- intent heads (gugi folded in) -------------------------------
__global__ void __launch_bounds__(128) intent_kernel(const int* __restrict__ root_u,
                                                     const int* __restrict__ root_i,
                                                     const float* __restrict__ ue,
                                                     const float* __restrict__ ie,
                                                     const float* __restrict__ w1,
                                                     const float* __restrict__ b1,
                                                     const float* __restrict__ w2,
                                                     const float* __restrict__ b2,
                                                     const float* __restrict__ c_u,
                                                     const float* __restrict__ c_v,
                                                     float* __restrict__ out, int out_size) {
    __shared__ float xs[DIM];
    __shared__ float h1[DIM];
    __shared__ float lg[KINT];
    __shared__ float ps[KINT];
    int side = blockIdx.x >> 10;
    int b = blockIdx.x & 1023;
    int j = threadIdx.x;

    // fold of gugi: repr = emb + relu(aggr)
    int node = side ? (root_i[b] + N_USERS) : root_u[b];
    const float* emb = (node < N_USERS) ? (ue + (size_t)node * DIM)
                                        : (ie + (size_t)(node - N_USERS) * DIM);
    float ev = emb[j];
    float av = g_aggr[(size_t)node * DIM + j];
    float r0 = ev + fmaxf(av, 0.f);
    xs[j] = r0;
    (side ? g_gi : g_gu)[b * DIM + j] = r0;
    if (!side && out_size >= OUT_TOTAL) out[OUT_GU + b * DIM + j] = r0;
    __syncthreads();

    float a = b1[j];
#pragma unroll 8
    for (int k = 0; k < DIM; k++) a += xs[k] * w1[k * DIM + j];
    h1[j] = tanhf(a);
    __syncthreads();
    if (j < KINT) {
        float l = b2[j];
        for (int k = 0; k < DIM; k++) l += h1[k] * w2[k * KINT + j];
        lg[j] = l;
    }
    __syncthreads();
    if (j == 0) {
        float m = lg[0];
        for (int t = 1; t < KINT; t++) m = fmaxf(m, lg[t]);
        float s = 0.f;
        for (int t = 0; t < KINT; t++) { ps[t] = expf(lg[t] - m); s += ps[t]; }
        float inv = 1.f / s;
        for (int t = 0; t < KINT; t++) ps[t] *= inv;
    }
    __syncthreads();
    const float* proto = side ? c_v : c_u;
    float r = 0.f;
#pragma unroll
    for (int t = 0; t < KINT; t++) r += ps[t] * proto[t * DIM + j];
    (side ? g_rv : g_ru)[b * DIM + j] = r;
    if (j < KINT && out_size >= OUT_TOTAL)
        out[(side ? OUT_PV : OUT_PU) + b * KINT + j] = ps[j];
}

// ---------------- PG = local_proj_w @ gcn_w ----------------------------------
__global__ void __launch_bounds__(128) pg_kernel(const float* __restrict__ P,
                                                 const float* __restrict__ Pb,
                                                 const float* __restrict__ G) {
    __shared__ float prow[DIM];
    int m = blockIdx.x;
    int j = threadIdx.x;
    prow[j] = (m < 256) ? P[m * DIM + j] : Pb[j];
    __syncthreads();
    float a = 0.f;
#pragma unroll 8
    for (int k = 0; k < DIM; k++) a += prow[k] * G[k * DIM + j];
    g_PG[m * DIM + j] = a;
}

__global__ void __launch_bounds__(128) d4_kernel(const float* __restrict__ dist_emb) {
    __shared__ float de[DIM];
    int d = blockIdx.x;
    int j = threadIdx.x;
    de[j] = dist_emb[d * DIM + j];
    __syncthreads();
    float a = g_PG[256 * DIM + j];
#pragma unroll 8
    for (int k = 0; k < DIM; k++) a += de[k] * g_PG[(128 + k) * DIM + j];
    g_D4[d * DIM + j] = a;
}

// ---------------- xw = repr(x_idx) @ PG_top + D4[dist_label]  (tf32 TC) ------
__global__ void __launch_bounds__(256) xw_gemm_tc(const int* __restrict__ x_idx,
                                                  const int* __restrict__ dist_label,
                                                  const float* __restrict__ ue,
                                                  const float* __restrict__ ie) {
    extern __shared__ float sm[];
    float* Wsm = sm;
    float* Xsm = sm + 128 * XS;
    int tid = threadIdx.x;
    int r0 = blockIdx.x * 128;

#pragma unroll
    for (int t = 0; t < 16; t++) {
        int i = tid + t * 256;
        int row = i >> 5, q = i & 31;
        float4 v = ((const float4*)g_PG)[row * 32 + q];
        *(float4*)&Wsm[row * XS + q * 4] = v;
    }
#pragma unroll
    for (int t = 0; t < 16; t++) {
        int i = tid + t * 256;
        int row = i >> 5, q = i & 31;
        int r = r0 + row;
        int node = x_idx[r];
        const float* p = (node < N_USERS) ? (ue + (size_t)node * DIM)
                                          : (ie + (size_t)(node - N_USERS) * DIM);
        float4 e4 = ((const float4*)p)[q];
        float4 a4 = ((const float4*)g_aggr)[(size_t)node * 32 + q];
        float4 v = make_float4(e4.x + fmaxf(a4.x, 0.f), e4.y + fmaxf(a4.y, 0.f),
                               e4.z + fmaxf(a4.z, 0.f), e4.w + fmaxf(a4.w, 0.f));
        *(float4*)&Xsm[row * XS + q * 4] = v;
    }
    __syncthreads();

    int warp = tid >> 5, lane = tid & 31;
    int gid = lane >> 2, tig = lane & 3;
    int wr = warp * 16;

    float acc[16][4];
#pragma unroll
    for (int n = 0; n < 16; n++)
#pragma unroll
        for (int m = 0; m < 4; m++) acc[n][m] = 0.f;

#pragma unroll
    for (int k = 0; k < 128; k += 8) {
        unsigned a0 = f2tf32(Xsm[(wr + gid) * XS + k + tig]);
        unsigned a1 = f2tf32(Xsm[(wr + gid + 8) * XS + k + tig]);
        unsigned a2 = f2tf32(Xsm[(wr + gid) * XS + k + tig + 4]);
        unsigned a3 = f2tf32(Xsm[(wr + gid + 8) * XS + k + tig + 4]);
#pragma unroll
        for (int n = 0; n < 16; n++) {
            unsigned b0 = f2tf32(Wsm[(k + tig) * XS + n * 8 + gid]);
            unsigned b1 = f2tf32(Wsm[(k + tig + 4) * XS + n * 8 + gid]);
            mma_tf32(acc[n], a0, a1, a2, a3, b0, b1);
        }
    }

    int row0 = r0 + wr + gid;
    int row1 = row0 + 8;
    int dl0 = dist_label[row0];
    int dl1 = dist_label[row1];
#pragma unroll
    for (int n = 0; n < 16; n++) {
        int c0 = n * 8 + tig * 2;
        float2 dv0 = *(const float2*)&g_D4[dl0 * DIM + c0];
        float2 dv1 = *(const float2*)&g_D4[dl1 * DIM + c0];
        float2 o0 = make_float2(acc[n][0] + dv0.x, acc[n][1] + dv0.y);
        float2 o1 = make_float2(acc[n][2] + dv1.x, acc[n][3] + dv1.y);
        *(float2*)&g_xw[(size_t)row0 * DIM + c0] = o0;
        *(float2*)&g_xw[(size_t)row1 * DIM + c0] = o1;
    }
}

// ---------------- local GCN gather: lout[d] = dinv[d]*(Σ dinv[s]xw[s] + dinv[d]xw[d])
__global__ void __launch_bounds__(256) lgather_kernel() {
    int warp = (blockIdx.x * blockDim.x + threadIdx.x) >> 5;
    int lane = threadIdx.x & 31;
    if (warp >= NL) return;
    int p   = g_lcnt[warp];
    int end = g_lcur[warp];
    float dd = g_dinv[warp];
    float4 sv = ((const float4*)g_xw)[(size_t)warp * 32 + lane];
    float4 acc = make_float4(dd * sv.x, dd * sv.y, dd * sv.z, dd * sv.w);  // self loop
    for (; p + 1 < end; p += 2) {
        int s0 = g_lpack[p];
        int s1 = g_lpack[p + 1];
        float4 v0 = ((const float4*)g_xw)[(size_t)s0 * 32 + lane];
        float4 v1 = ((const float4*)g_xw)[(size_t)s1 * 32 + lane];
        float n0 = g_dinv[s0];
        float n1 = g_dinv[s1];
        acc.x += n0 * v0.x + n1 * v1.x;
        acc.y += n0 * v0.y + n1 * v1.y;
        acc.z += n0 * v0.z + n1 * v1.z;
        acc.w += n0 * v0.w + n1 * v1.w;
    }
    if (p < end) {
        int s = g_lpack[p];
        float4 v = ((const float4*)g_xw)[(size_t)s * 32 + lane];
        float n = g_dinv[s];
        acc.x += n * v.x; acc.y += n * v.y; acc.z += n * v.z; acc.w += n * v.w;
    }
    acc.x *= dd; acc.y *= dd; acc.z *= dd; acc.w *= dd;
    ((float4*)g_lout)[(size_t)warp * 32 + lane] = acc;
}

// ---------------- pool + final MLP fused (same block index b) -----------------
__device__ int lower_bound_i(const int* a, int n, int v) {
    int lo = 0, hi = n;
    while (lo < hi) { int m = (lo + hi) >> 1; if (a[m] < v) lo = m + 1; else hi = m; }
    return lo;
}
__global__ void __launch_bounds__(128) pool_final_kernel(const int* __restrict__ batch,
                                                         const float* __restrict__ gcn_b,
                                                         const float* __restrict__ pool_w,
                                                         const float* __restrict__ pool_b,
                                                         const float* __restrict__ w1,
                                                         const float* __restrict__ b1,
                                                         const float* __restrict__ w2,
                                                         const float* __restrict__ b2,
                                                         float* __restrict__ out, int out_size) {
    __shared__ int seg[2];
    __shared__ float mean[DIM];
    __shared__ float v[4 * DIM];
    __shared__ float hid[64];
    int b = blockIdx.x;
    int j = threadIdx.x;
    if (j == 0) seg[0] = lower_bound_i(batch, NL, b);
    if (j == 1) seg[1] = lower_bound_i(batch, NL, b + 1);
    __syncthreads();
    int lo = seg[0], hi = seg[1];
    float acc = 0.f;
    for (int i = lo; i < hi; i++)
        acc += g_lout[(size_t)i * DIM + j];
    int cnt = hi - lo;
    mean[j] = (cnt > 0) ? (acc / (float)cnt + gcn_b[j]) : 0.f;
    __syncthreads();
    float t = pool_b[j];
#pragma unroll 8
    for (int k = 0; k < DIM; k++) t += mean[k] * pool_w[k * DIM + j];
    float h = tanhf(t);
    if (out_size >= OUT_TOTAL) out[OUT_HSUB + b * DIM + j] = h;

    // final MLP for this b (hsub stays in smem)
    v[j]           = h;
    v[DIM + j]     = g_gu[b * DIM + j];
    v[2 * DIM + j] = g_gi[b * DIM + j];
    v[3 * DIM + j] = g_ru[b * DIM + j] * g_rv[b * DIM + j];
    __syncthreads();
    if (j < 64) {
        float a = b1[j];
#pragma unroll 8
        for (int k = 0; k < 4 * DIM; k++) a += v[k] * w1[k * 64 + j];
        hid[j] = fmaxf(a, 0.f) * w2[j];
    }
    __syncthreads();
    if (j == 0) {
        float s = b2[0];
        for (int tte = 0; tte < 64; tte++) s += hid[tte];
        out[OUT_PRED + b] = 1.f / (1.f + expf(-s));
    }
}

// ---------------- launch ------------------------------------------------------
extern "C" void kernel_launch(void* const* d_in, const int* in_sizes, int n_in,
                              void* d_out, int out_size) {
    const int*   gei    = (const int*)d_in[0];
    const int*   gea    = (const int*)d_in[1];
    const int*   root_u = (const int*)d_in[2];
    const int*   root_i = (const int*)d_in[3];
    const int*   x_idx  = (const int*)d_in[4];
    const int*   dist_l = (const int*)d_in[5];
    const int*   lei    = (const int*)d_in[6];
    const int*   batch  = (const int*)d_in[7];
    const float* ue     = (const float*)d_in[8];
    const float* ie     = (const float*)d_in[9];
    const float* dist_e = (const float*)d_in[10];
    const float* c_u    = (const float*)d_in[11];
    const float* c_v    = (const float*)d_in[12];
    const float* gnn_W  = (const float*)d_in[13];
    const float* gnn_b  = (const float*)d_in[14];
    const float* sign_e = (const float*)d_in[15];
    const float* iw1    = (const float*)d_in[16];
    const float* ib1    = (const float*)d_in[17];
    const float* iw2    = (const float*)d_in[18];
    const float* ib2    = (const float*)d_in[19];
    const float* lpw    = (const float*)d_in[20];
    const float* lpb    = (const float*)d_in[21];
    const float* gcw    = (const float*)d_in[22];
    const float* gcb    = (const float*)d_in[23];
    const float* pow_   = (const float*)d_in[24];
    const float* pob    = (const float*)d_in[25];
    const float* fw1    = (const float*)d_in[26];
    const float* fb1    = (const float*)d_in[27];
    const float* fw2    = (const float*)d_in[28];
    const float* fb2    = (const float*)d_in[29];
    float* out = (float*)d_out;

    // Created once on the (uncaptured) correctness call; kept alive for capture.
    static cudaStream_t sA = nullptr;
    static cudaEvent_t evStart, evA;
    if (sA == nullptr) {
        cudaStreamCreateWithFlags(&sA, cudaStreamNonBlocking);
        cudaEventCreateWithFlags(&evStart, cudaEventDisableTiming);
        cudaEventCreateWithFlags(&evA,     cudaEventDisableTiming);
        cudaFuncSetAttribute(y_gemm_tc,  cudaFuncAttributeMaxDynamicSharedMemorySize, GEMM_SMEM);
        cudaFuncSetAttribute(xw_gemm_tc, cudaFuncAttributeMaxDynamicSharedMemorySize, GEMM_SMEM);
    }

    cudaEventRecord(evStart, 0);

    // stream A (fork): y_gemm + PG/D4 — independent of the CSR build
    cudaStreamWaitEvent(sA, evStart, 0);
    y_gemm_tc<<<(N_NODES + 127) / 128, 256, GEMM_SMEM, sA>>>(ue, ie, gnn_W, gnn_b);
    pg_kernel<<<257, 128, 0, sA>>>(lpw, lpb, gcw);
    d4_kernel<<<4, 128, 0, sA>>>(dist_e);
    cudaEventRecord(evA, sA);

    // main stream: CSR build (global + local merged)
    init_cnt_kernel<<<592, 256>>>();
    hist_both<<<(E_G + EL + 255) / 256, 256>>>(gei + E_G, lei + EL);
    scan_a_both<<<NSEG_G + NSEG_L, SCAN_B>>>();
    scan_c_both<<<NSEG_G + NSEG_L, SCAN_B>>>();
    fill_both<<<(E_G + EL + 255) / 256, 256>>>(gei, gei + E_G, gea, lei, lei + EL);

    // join: gather needs CSR (main) + Y (stream A); xw later needs PG/D4 (also evA)
    cudaStreamWaitEvent(0, evA, 0);
    gather_aggr<<<(N_NODES * 32 + 255) / 256, 256>>>(sign_e);

    intent_kernel<<<2 * BATCH, 128>>>(root_u, root_i, ue, ie,
                                      iw1, ib1, iw2, ib2, c_u, c_v, out, out_size);

    xw_gemm_tc<<<NL / 128, 256, GEMM_SMEM>>>(x_idx, dist_l, ue, ie);

    lgather_kernel<<<(NL * 32) / 256, 256>>>();
    pool_final_kernel<<<BATCH, 128>>>(batch, gcb, pow_, pob,
                                      fw1, fb1, fw2, fb2, out, out_size);
}